// round 1
// baseline (speedup 1.0000x reference)
#include <cuda_runtime.h>
#include <math.h>

#define EMBED   1024
#define SEQ     1024
#define BATCH   8
#define NTOK    (BATCH * SEQ)      // 8192
#define HIDDEN  4096
#define HEADS   16
#define HDIM    64
#define QKV3    (3 * EMBED)        // 3072

// ---------------- scratch (no cudaMalloc allowed) ----------------
__device__ float g_ln [NTOK * EMBED];     // 32 MB (reused ln1/ln2)
__device__ float g_qkv[NTOK * QKV3];      // 96 MB
__device__ float g_y  [NTOK * EMBED];     // 32 MB
__device__ float g_x1 [NTOK * EMBED];     // 32 MB
__device__ float g_h  [NTOK * HIDDEN];    // 128 MB

// ---------------- LayerNorm: one block per row (1024 cols) ----------------
__global__ void ln_kernel(const float* __restrict__ x,
                          const float* __restrict__ g,
                          const float* __restrict__ b,
                          float* __restrict__ out)
{
    int row = blockIdx.x;
    int t   = threadIdx.x;                 // 256 threads, 4 floats each
    const float4* xr = (const float4*)(x + (size_t)row * EMBED);
    float4 v = xr[t];

    float s  = v.x + v.y + v.z + v.w;
    float s2 = v.x*v.x + v.y*v.y + v.z*v.z + v.w*v.w;

    // warp reduce
    #pragma unroll
    for (int off = 16; off > 0; off >>= 1) {
        s  += __shfl_xor_sync(0xffffffffu, s,  off);
        s2 += __shfl_xor_sync(0xffffffffu, s2, off);
    }
    __shared__ float red1[8], red2[8];
    int wid = t >> 5, lane = t & 31;
    if (lane == 0) { red1[wid] = s; red2[wid] = s2; }
    __syncthreads();
    __shared__ float s_mu, s_rstd;
    if (t == 0) {
        float ts = 0.f, ts2 = 0.f;
        #pragma unroll
        for (int i = 0; i < 8; i++) { ts += red1[i]; ts2 += red2[i]; }
        float mu  = ts * (1.0f / EMBED);
        float var = ts2 * (1.0f / EMBED) - mu * mu;
        s_mu = mu;
        s_rstd = rsqrtf(var + 1e-5f);
    }
    __syncthreads();
    float mu = s_mu, rstd = s_rstd;

    float4 gv = ((const float4*)g)[t];
    float4 bv = ((const float4*)b)[t];
    float4 o;
    o.x = (v.x - mu) * rstd * gv.x + bv.x;
    o.y = (v.y - mu) * rstd * gv.y + bv.y;
    o.z = (v.z - mu) * rstd * gv.z + bv.z;
    o.w = (v.w - mu) * rstd * gv.w + bv.w;
    ((float4*)(out + (size_t)row * EMBED))[t] = o;
}

// ---------------- fp32 GEMM: C[M,N] = A[M,K]@B[K,N] (+bias)(+res)(relu) ----
// 128x128 tile, Ktile=16, 256 threads, 8x8 per thread.
template<bool BIAS, bool RELU, bool RES>
__global__ void __launch_bounds__(256, 2)
gemm_kernel(const float* __restrict__ A, const float* __restrict__ B,
            const float* __restrict__ bias, const float* __restrict__ res,
            float* __restrict__ C, int M, int N, int K)
{
    __shared__ float As[16][128];
    __shared__ float Bs[16][128];

    int tid = threadIdx.x;
    int tx = tid & 15, ty = tid >> 4;
    int m0 = blockIdx.y * 128, n0 = blockIdx.x * 128;

    float acc[8][8];
    #pragma unroll
    for (int i = 0; i < 8; i++)
        #pragma unroll
        for (int j = 0; j < 8; j++) acc[i][j] = 0.f;

    for (int kt = 0; kt < K; kt += 16) {
        #pragma unroll
        for (int r = 0; r < 2; r++) {
            int i = tid + r * 256;
            // A tile: 128 rows x 16 k, transposed into As[k][m]
            int arow = i >> 2;
            int acol = (i & 3) * 4;
            float4 av = *(const float4*)(A + (size_t)(m0 + arow) * K + kt + acol);
            As[acol + 0][arow] = av.x;
            As[acol + 1][arow] = av.y;
            As[acol + 2][arow] = av.z;
            As[acol + 3][arow] = av.w;
            // B tile: 16 k x 128 n
            int brow = i >> 5;
            int bcol = (i & 31) * 4;
            *(float4*)&Bs[brow][bcol] =
                *(const float4*)(B + (size_t)(kt + brow) * N + n0 + bcol);
        }
        __syncthreads();

        #pragma unroll
        for (int k = 0; k < 16; k++) {
            float4 a0 = *(float4*)&As[k][ty * 8];
            float4 a1 = *(float4*)&As[k][ty * 8 + 4];
            float4 b0 = *(float4*)&Bs[k][tx * 8];
            float4 b1 = *(float4*)&Bs[k][tx * 8 + 4];
            float ra[8] = {a0.x, a0.y, a0.z, a0.w, a1.x, a1.y, a1.z, a1.w};
            float rb[8] = {b0.x, b0.y, b0.z, b0.w, b1.x, b1.y, b1.z, b1.w};
            #pragma unroll
            for (int i = 0; i < 8; i++)
                #pragma unroll
                for (int j = 0; j < 8; j++)
                    acc[i][j] = fmaf(ra[i], rb[j], acc[i][j]);
        }
        __syncthreads();
    }

    // epilogue
    #pragma unroll
    for (int i = 0; i < 8; i++) {
        int m = m0 + ty * 8 + i;
        #pragma unroll
        for (int jj = 0; jj < 2; jj++) {
            int n = n0 + tx * 8 + jj * 4;
            float4 c;
            c.x = acc[i][jj*4+0]; c.y = acc[i][jj*4+1];
            c.z = acc[i][jj*4+2]; c.w = acc[i][jj*4+3];
            if (BIAS) {
                float4 bv = *(const float4*)(bias + n);
                c.x += bv.x; c.y += bv.y; c.z += bv.z; c.w += bv.w;
            }
            if (RES) {
                float4 rv = *(const float4*)(res + (size_t)m * N + n);
                c.x += rv.x; c.y += rv.y; c.z += rv.z; c.w += rv.w;
            }
            if (RELU) {
                c.x = fmaxf(c.x, 0.f); c.y = fmaxf(c.y, 0.f);
                c.z = fmaxf(c.z, 0.f); c.w = fmaxf(c.w, 0.f);
            }
            *(float4*)(C + (size_t)m * N + n) = c;
        }
    }
}

// ---------------- flash attention: BQ=64, BK=32, D=64 ----------------
// grid: (qtiles=16, heads=16, batch=8); 256 threads (16x16).
__global__ void __launch_bounds__(256)
attn_kernel(const float* __restrict__ qkv, float* __restrict__ y)
{
    __shared__ float Qs[64][65];
    __shared__ float Ks[32][65];
    __shared__ float Vs[32][65];
    __shared__ float Ps[64][33];

    int qt = blockIdx.x, h = blockIdx.y, b = blockIdx.z;
    int tid = threadIdx.x;
    int tx = tid & 15, ty = tid >> 4;
    const float scale = 0.125f;   // 1/sqrt(64)

    size_t base = ((size_t)b * SEQ) * QKV3 + (size_t)h * HDIM;

    // load Q tile (scaled)
    #pragma unroll
    for (int r = 0; r < 4; r++) {
        int i = tid + r * 256;            // 0..1023
        int qr = i >> 4;
        int dd = (i & 15) * 4;
        float4 qv = *(const float4*)(qkv + base + (size_t)(qt * 64 + qr) * QKV3 + dd);
        Qs[qr][dd + 0] = qv.x * scale;
        Qs[qr][dd + 1] = qv.y * scale;
        Qs[qr][dd + 2] = qv.z * scale;
        Qs[qr][dd + 3] = qv.w * scale;
    }

    float m[4], l[4], o[4][4];
    #pragma unroll
    for (int i = 0; i < 4; i++) {
        m[i] = -1e30f; l[i] = 0.f;
        #pragma unroll
        for (int j = 0; j < 4; j++) o[i][j] = 0.f;
    }

    for (int kt = 0; kt < SEQ; kt += 32) {
        __syncthreads();   // previous-iter Ps/Vs readers done
        // load K,V tile (32x64 each)
        #pragma unroll
        for (int r = 0; r < 2; r++) {
            int i = tid + r * 256;        // 0..511
            int kr = i >> 4;
            int dd = (i & 15) * 4;
            const float* kp = qkv + base + (size_t)(kt + kr) * QKV3 + EMBED + dd;
            float4 kv = *(const float4*)kp;
            Ks[kr][dd + 0] = kv.x; Ks[kr][dd + 1] = kv.y;
            Ks[kr][dd + 2] = kv.z; Ks[kr][dd + 3] = kv.w;
            float4 vv = *(const float4*)(kp + EMBED);
            Vs[kr][dd + 0] = vv.x; Vs[kr][dd + 1] = vv.y;
            Vs[kr][dd + 2] = vv.z; Vs[kr][dd + 3] = vv.w;
        }
        __syncthreads();

        // S = Q K^T : each thread 4 q-rows x 2 k-cols
        float s[4][2] = {{0.f,0.f},{0.f,0.f},{0.f,0.f},{0.f,0.f}};
        #pragma unroll 16
        for (int d = 0; d < 64; d++) {
            float k0 = Ks[tx * 2 + 0][d];
            float k1 = Ks[tx * 2 + 1][d];
            #pragma unroll
            for (int i = 0; i < 4; i++) {
                float q = Qs[ty * 4 + i][d];
                s[i][0] = fmaf(q, k0, s[i][0]);
                s[i][1] = fmaf(q, k1, s[i][1]);
            }
        }

        // online softmax per q-row (row spread across the 16 tx threads)
        #pragma unroll
        for (int i = 0; i < 4; i++) {
            float rm = fmaxf(s[i][0], s[i][1]);
            #pragma unroll
            for (int off = 1; off < 16; off <<= 1)
                rm = fmaxf(rm, __shfl_xor_sync(0xffffffffu, rm, off));
            float mn = fmaxf(m[i], rm);
            float alpha = __expf(m[i] - mn);
            float p0 = __expf(s[i][0] - mn);
            float p1 = __expf(s[i][1] - mn);
            float rs = p0 + p1;
            #pragma unroll
            for (int off = 1; off < 16; off <<= 1)
                rs += __shfl_xor_sync(0xffffffffu, rs, off);
            l[i] = l[i] * alpha + rs;
            m[i] = mn;
            #pragma unroll
            for (int j = 0; j < 4; j++) o[i][j] *= alpha;
            Ps[ty * 4 + i][tx * 2 + 0] = p0;
            Ps[ty * 4 + i][tx * 2 + 1] = p1;
        }
        __syncthreads();

        // O += P @ V : each thread 4 q-rows x 4 d-cols (dcol = tx*4+j)
        #pragma unroll 8
        for (int kk = 0; kk < 32; kk++) {
            float v0 = Vs[kk][tx * 4 + 0];
            float v1 = Vs[kk][tx * 4 + 1];
            float v2 = Vs[kk][tx * 4 + 2];
            float v3 = Vs[kk][tx * 4 + 3];
            #pragma unroll
            for (int i = 0; i < 4; i++) {
                float p = Ps[ty * 4 + i][kk];
                o[i][0] = fmaf(p, v0, o[i][0]);
                o[i][1] = fmaf(p, v1, o[i][1]);
                o[i][2] = fmaf(p, v2, o[i][2]);
                o[i][3] = fmaf(p, v3, o[i][3]);
            }
        }
    }

    // write y[b, t, h, d]
    #pragma unroll
    for (int i = 0; i < 4; i++) {
        float inv = 1.0f / l[i];
        int row = qt * 64 + ty * 4 + i;
        float4 ov;
        ov.x = o[i][0] * inv; ov.y = o[i][1] * inv;
        ov.z = o[i][2] * inv; ov.w = o[i][3] * inv;
        *(float4*)(y + ((size_t)b * SEQ + row) * EMBED + h * HDIM + tx * 4) = ov;
    }
}

// ---------------- launch ----------------
extern "C" void kernel_launch(void* const* d_in, const int* in_sizes, int n_in,
                              void* d_out, int out_size)
{
    (void)in_sizes; (void)n_in; (void)out_size;
    const float* x     = (const float*)d_in[0];
    const float* ln1_g = (const float*)d_in[1];
    const float* ln1_b = (const float*)d_in[2];
    const float* w_qkv = (const float*)d_in[3];
    const float* b_qkv = (const float*)d_in[4];
    const float* w_out = (const float*)d_in[5];
    const float* b_out = (const float*)d_in[6];
    const float* ln2_g = (const float*)d_in[7];
    const float* ln2_b = (const float*)d_in[8];
    const float* w_up  = (const float*)d_in[9];
    const float* b_up  = (const float*)d_in[10];
    const float* w_down= (const float*)d_in[11];
    const float* b_down= (const float*)d_in[12];
    float* out = (float*)d_out;

    float *p_ln, *p_qkv, *p_y, *p_x1, *p_h;
    cudaGetSymbolAddress((void**)&p_ln,  g_ln);
    cudaGetSymbolAddress((void**)&p_qkv, g_qkv);
    cudaGetSymbolAddress((void**)&p_y,   g_y);
    cudaGetSymbolAddress((void**)&p_x1,  g_x1);
    cudaGetSymbolAddress((void**)&p_h,   g_h);

    // 1) ln1
    ln_kernel<<<NTOK, 256>>>(x, ln1_g, ln1_b, p_ln);
    // 2) qkv = ln1 @ w_qkv + b_qkv
    gemm_kernel<true,false,false><<<dim3(QKV3/128, NTOK/128), 256>>>(
        p_ln, w_qkv, b_qkv, nullptr, p_qkv, NTOK, QKV3, EMBED);
    // 3) attention
    attn_kernel<<<dim3(SEQ/64, HEADS, BATCH), 256>>>(p_qkv, p_y);
    // 4) x1 = x + y @ w_out + b_out
    gemm_kernel<true,false,true><<<dim3(EMBED/128, NTOK/128), 256>>>(
        p_y, w_out, b_out, x, p_x1, NTOK, EMBED, EMBED);
    // 5) ln2
    ln_kernel<<<NTOK, 256>>>(p_x1, ln2_g, ln2_b, p_ln);
    // 6) h = relu(ln2 @ w_up + b_up)
    gemm_kernel<true,true,false><<<dim3(HIDDEN/128, NTOK/128), 256>>>(
        p_ln, w_up, b_up, nullptr, p_h, NTOK, HIDDEN, EMBED);
    // 7) out = x1 + h @ w_down + b_down
    gemm_kernel<true,false,true><<<dim3(EMBED/128, NTOK/128), 256>>>(
        p_h, w_down, b_down, p_x1, out, NTOK, EMBED, HIDDEN);
}

// round 3
// speedup vs baseline: 2.2982x; 2.2982x over previous
#include <cuda_runtime.h>
#include <cstdint>
#include <math.h>

#define EMBED   1024
#define SEQ     1024
#define BATCH   8
#define NTOK    8192
#define HIDDEN  4096
#define HEADS   16
#define HDIM    64
#define QKV3    3072

// ---------------- scratch (no cudaMalloc allowed) ----------------
__device__ float g_ln    [NTOK * EMBED];
__device__ float g_qkv   [(size_t)NTOK * QKV3];
__device__ float g_y     [NTOK * EMBED];
__device__ float g_x1    [NTOK * EMBED];
__device__ float g_h     [(size_t)NTOK * HIDDEN];
__device__ float g_wqkvT [(size_t)QKV3 * EMBED];
__device__ float g_woutT [(size_t)EMBED * EMBED];
__device__ float g_wupT  [(size_t)HIDDEN * EMBED];
__device__ float g_wdownT[(size_t)EMBED * HIDDEN];

// ---------------- helpers ----------------
__device__ __forceinline__ uint32_t smem_u32(const void* p) {
    uint32_t a;
    asm("{ .reg .u64 t; cvta.to.shared.u64 t, %1; cvt.u32.u64 %0, t; }" : "=r"(a) : "l"(p));
    return a;
}
__device__ __forceinline__ float tf32_rna(float x) {
    uint32_t u;
    asm("cvt.rna.tf32.f32 %0, %1;" : "=r"(u) : "f"(x));
    return __uint_as_float(u);
}
__device__ __forceinline__ void cp_async16(uint32_t dst, const void* src) {
    asm volatile("cp.async.cg.shared.global [%0], [%1], 16;" :: "r"(dst), "l"(src) : "memory");
}
#define CP_COMMIT() asm volatile("cp.async.commit_group;" ::: "memory")
template <int N>
__device__ __forceinline__ void cp_wait() {
    asm volatile("cp.async.wait_group %0;" :: "n"(N) : "memory");
}

// m16n8k8 tf32 mma (sm_80+ portable PTX; compiles for compute_103)
__device__ __forceinline__ void mma_tf32(float* c, const uint32_t* a, const uint32_t* b) {
    asm volatile(
        "mma.sync.aligned.m16n8k8.row.col.f32.tf32.tf32.f32 "
        "{%0,%1,%2,%3}, {%4,%5,%6,%7}, {%8,%9}, {%0,%1,%2,%3};"
        : "+f"(c[0]), "+f"(c[1]), "+f"(c[2]), "+f"(c[3])
        : "r"(a[0]), "r"(a[1]), "r"(a[2]), "r"(a[3]), "r"(b[0]), "r"(b[1]));
}

// ---------------- tf32 tensor-core GEMM ----------------
// C[M,N] = A[M,K] @ Bt[N,K]^T (+bias)(+res)(relu)(round)
// CTA tile 128M x 256N x 32K, 8 warps (2x4) each 64x64, 3-stage cp.async.
#define BM 128
#define BN 256
#define BK 32
#define PITCH 36                 // 36 mod 32 = 4 -> conflict-free fragment LDS
#define A_F   (BM * PITCH)       // 4608 floats
#define B_F   (BN * PITCH)       // 9216 floats
#define STAGE_F (A_F + B_F)      // 13824 floats
#define NSTAGE 3
#define SMEM_DYN (NSTAGE * STAGE_F * 4)   // 165888 bytes

template<bool RELU, bool RES, bool ROUND>
__global__ void __launch_bounds__(256, 1)
gemm_mma(const float* __restrict__ A, const float* __restrict__ Bt,
         const float* __restrict__ bias, const float* __restrict__ res,
         float* __restrict__ C, int N, int K)
{
    extern __shared__ float sm[];
    const uint32_t sbase = smem_u32(sm);
    const int tid  = threadIdx.x;
    const int wid  = tid >> 5, lane = tid & 31;
    const int gq   = lane >> 2, tq = lane & 3;        // group / thread-in-group
    const int wm   = wid >> 2,  wn = wid & 3;         // warp 2x4
    const int m0   = blockIdx.y * BM, n0 = blockIdx.x * BN;
    const int nk   = K / BK;

    float acc[4][8][4];
    #pragma unroll
    for (int i = 0; i < 4; i++)
        #pragma unroll
        for (int j = 0; j < 8; j++)
            #pragma unroll
            for (int q = 0; q < 4; q++) acc[i][j][q] = 0.f;

    const float* Ag0 = A  + (size_t)m0 * K;
    const float* Bg0 = Bt + (size_t)n0 * K;

    auto load_stage = [&](int s, int kt) {
        uint32_t sa = sbase + (uint32_t)s * (STAGE_F * 4);
        const float* Ag = Ag0 + kt * BK;
        #pragma unroll
        for (int j = 0; j < 4; j++) {
            int c = tid + j * 256;            // 0..1023
            int row = c >> 3, kc = c & 7;
            cp_async16(sa + (uint32_t)(row * PITCH + kc * 4) * 4,
                       Ag + (size_t)row * K + kc * 4);
        }
        uint32_t sb = sa + A_F * 4;
        const float* Bg = Bg0 + kt * BK;
        #pragma unroll
        for (int j = 0; j < 8; j++) {
            int c = tid + j * 256;            // 0..2047
            int row = c >> 3, kc = c & 7;
            cp_async16(sb + (uint32_t)(row * PITCH + kc * 4) * 4,
                       Bg + (size_t)row * K + kc * 4);
        }
        CP_COMMIT();
    };

    load_stage(0, 0);
    load_stage(1, 1);

    for (int kt = 0; kt < nk; kt++) {
        if (kt + 2 < nk) { load_stage((kt + 2) % NSTAGE, kt + 2); cp_wait<2>(); }
        else if (kt + 1 < nk) cp_wait<1>();
        else cp_wait<0>();
        __syncthreads();

        const uint32_t* a_s = (const uint32_t*)(sm + (kt % NSTAGE) * STAGE_F);
        const uint32_t* b_s = a_s + A_F;

        #pragma unroll
        for (int ks = 0; ks < 4; ks++) {
            const int k8 = ks * 8;
            uint32_t af[4][4];
            #pragma unroll
            for (int mi = 0; mi < 4; mi++) {
                int rb = wm * 64 + mi * 16;
                af[mi][0] = a_s[(rb + gq)     * PITCH + k8 + tq];
                af[mi][1] = a_s[(rb + gq + 8) * PITCH + k8 + tq];
                af[mi][2] = a_s[(rb + gq)     * PITCH + k8 + tq + 4];
                af[mi][3] = a_s[(rb + gq + 8) * PITCH + k8 + tq + 4];
            }
            uint32_t bf[8][2];
            #pragma unroll
            for (int ni = 0; ni < 8; ni++) {
                int nb = wn * 64 + ni * 8;
                bf[ni][0] = b_s[(nb + gq) * PITCH + k8 + tq];
                bf[ni][1] = b_s[(nb + gq) * PITCH + k8 + tq + 4];
            }
            #pragma unroll
            for (int mi = 0; mi < 4; mi++)
                #pragma unroll
                for (int ni = 0; ni < 8; ni++)
                    mma_tf32(acc[mi][ni], af[mi], bf[ni]);
        }
        __syncthreads();
    }

    // ---------- epilogue ----------
    #pragma unroll
    for (int ni = 0; ni < 8; ni++) {
        int col = n0 + wn * 64 + ni * 8 + 2 * tq;
        float2 bv = __ldg((const float2*)(bias + col));
        #pragma unroll
        for (int mi = 0; mi < 4; mi++) {
            int row = m0 + wm * 64 + mi * 16 + gq;
            float* c0p = C + (size_t)row * N + col;
            float* c1p = C + (size_t)(row + 8) * N + col;
            float2 v0, v1;
            v0.x = acc[mi][ni][0] + bv.x;
            v0.y = acc[mi][ni][1] + bv.y;
            v1.x = acc[mi][ni][2] + bv.x;
            v1.y = acc[mi][ni][3] + bv.y;
            if (RES) {
                float2 r0 = __ldg((const float2*)(res + (size_t)row * N + col));
                float2 r1 = __ldg((const float2*)(res + (size_t)(row + 8) * N + col));
                v0.x += r0.x; v0.y += r0.y;
                v1.x += r1.x; v1.y += r1.y;
            }
            if (RELU) {
                v0.x = fmaxf(v0.x, 0.f); v0.y = fmaxf(v0.y, 0.f);
                v1.x = fmaxf(v1.x, 0.f); v1.y = fmaxf(v1.y, 0.f);
            }
            if (ROUND) {
                v0.x = tf32_rna(v0.x); v0.y = tf32_rna(v0.y);
                v1.x = tf32_rna(v1.x); v1.y = tf32_rna(v1.y);
            }
            *(float2*)c0p = v0;
            *(float2*)c1p = v1;
        }
    }
}

// ---------------- weight transpose + tf32 round: in[K,N] -> out[N,K] ------
__global__ void transpose_rna(const float* __restrict__ in, float* __restrict__ out,
                              int K, int N)
{
    __shared__ float t[32][33];
    int n  = blockIdx.x * 32 + threadIdx.x;
    int k0 = blockIdx.y * 32;
    #pragma unroll
    for (int r = 0; r < 32; r += 8)
        t[threadIdx.y + r][threadIdx.x] = in[(size_t)(k0 + threadIdx.y + r) * N + n];
    __syncthreads();
    int k   = k0 + threadIdx.x;
    int nn0 = blockIdx.x * 32;
    #pragma unroll
    for (int r = 0; r < 32; r += 8)
        out[(size_t)(nn0 + threadIdx.y + r) * K + k] = tf32_rna(t[threadIdx.x][threadIdx.y + r]);
}

// ---------------- LayerNorm (output tf32-rounded: it only feeds GEMMs) ----
__global__ void ln_kernel(const float* __restrict__ x,
                          const float* __restrict__ g,
                          const float* __restrict__ b,
                          float* __restrict__ out)
{
    int row = blockIdx.x;
    int t   = threadIdx.x;
    const float4* xr = (const float4*)(x + (size_t)row * EMBED);
    float4 v = xr[t];

    float s  = v.x + v.y + v.z + v.w;
    float s2 = v.x*v.x + v.y*v.y + v.z*v.z + v.w*v.w;
    #pragma unroll
    for (int off = 16; off > 0; off >>= 1) {
        s  += __shfl_xor_sync(0xffffffffu, s,  off);
        s2 += __shfl_xor_sync(0xffffffffu, s2, off);
    }
    __shared__ float red1[8], red2[8];
    int wid = t >> 5, lane = t & 31;
    if (lane == 0) { red1[wid] = s; red2[wid] = s2; }
    __syncthreads();
    __shared__ float s_mu, s_rstd;
    if (t == 0) {
        float ts = 0.f, ts2 = 0.f;
        #pragma unroll
        for (int i = 0; i < 8; i++) { ts += red1[i]; ts2 += red2[i]; }
        float mu  = ts * (1.0f / EMBED);
        float var = ts2 * (1.0f / EMBED) - mu * mu;
        s_mu = mu; s_rstd = rsqrtf(var + 1e-5f);
    }
    __syncthreads();
    float mu = s_mu, rstd = s_rstd;

    float4 gv = ((const float4*)g)[t];
    float4 bv = ((const float4*)b)[t];
    float4 o;
    o.x = tf32_rna((v.x - mu) * rstd * gv.x + bv.x);
    o.y = tf32_rna((v.y - mu) * rstd * gv.y + bv.y);
    o.z = tf32_rna((v.z - mu) * rstd * gv.z + bv.z);
    o.w = tf32_rna((v.w - mu) * rstd * gv.w + bv.w);
    ((float4*)(out + (size_t)row * EMBED))[t] = o;
}

// ---------------- flash attention (fp32, y output tf32-rounded) ----------
__global__ void __launch_bounds__(256)
attn_kernel(const float* __restrict__ qkv, float* __restrict__ y)
{
    __shared__ float Qs[64][65];
    __shared__ float Ks[32][65];
    __shared__ float Vs[32][65];
    __shared__ float Ps[64][33];

    int qt = blockIdx.x, h = blockIdx.y, b = blockIdx.z;
    int tid = threadIdx.x;
    int tx = tid & 15, ty = tid >> 4;
    const float scale = 0.125f;

    size_t base = ((size_t)b * SEQ) * QKV3 + (size_t)h * HDIM;

    #pragma unroll
    for (int r = 0; r < 4; r++) {
        int i = tid + r * 256;
        int qr = i >> 4;
        int dd = (i & 15) * 4;
        float4 qv = *(const float4*)(qkv + base + (size_t)(qt * 64 + qr) * QKV3 + dd);
        Qs[qr][dd + 0] = qv.x * scale;
        Qs[qr][dd + 1] = qv.y * scale;
        Qs[qr][dd + 2] = qv.z * scale;
        Qs[qr][dd + 3] = qv.w * scale;
    }

    float m[4], l[4], o[4][4];
    #pragma unroll
    for (int i = 0; i < 4; i++) {
        m[i] = -1e30f; l[i] = 0.f;
        #pragma unroll
        for (int j = 0; j < 4; j++) o[i][j] = 0.f;
    }

    for (int kt = 0; kt < SEQ; kt += 32) {
        __syncthreads();
        #pragma unroll
        for (int r = 0; r < 2; r++) {
            int i = tid + r * 256;
            int kr = i >> 4;
            int dd = (i & 15) * 4;
            const float* kp = qkv + base + (size_t)(kt + kr) * QKV3 + EMBED + dd;
            float4 kv = *(const float4*)kp;
            Ks[kr][dd + 0] = kv.x; Ks[kr][dd + 1] = kv.y;
            Ks[kr][dd + 2] = kv.z; Ks[kr][dd + 3] = kv.w;
            float4 vv = *(const float4*)(kp + EMBED);
            Vs[kr][dd + 0] = vv.x; Vs[kr][dd + 1] = vv.y;
            Vs[kr][dd + 2] = vv.z; Vs[kr][dd + 3] = vv.w;
        }
        __syncthreads();

        float s[4][2] = {{0.f,0.f},{0.f,0.f},{0.f,0.f},{0.f,0.f}};
        #pragma unroll 16
        for (int d = 0; d < 64; d++) {
            float k0 = Ks[tx * 2 + 0][d];
            float k1 = Ks[tx * 2 + 1][d];
            #pragma unroll
            for (int i = 0; i < 4; i++) {
                float q = Qs[ty * 4 + i][d];
                s[i][0] = fmaf(q, k0, s[i][0]);
                s[i][1] = fmaf(q, k1, s[i][1]);
            }
        }

        #pragma unroll
        for (int i = 0; i < 4; i++) {
            float rm = fmaxf(s[i][0], s[i][1]);
            #pragma unroll
            for (int off = 1; off < 16; off <<= 1)
                rm = fmaxf(rm, __shfl_xor_sync(0xffffffffu, rm, off));
            float mn = fmaxf(m[i], rm);
            float alpha = __expf(m[i] - mn);
            float p0 = __expf(s[i][0] - mn);
            float p1 = __expf(s[i][1] - mn);
            float rs = p0 + p1;
            #pragma unroll
            for (int off = 1; off < 16; off <<= 1)
                rs += __shfl_xor_sync(0xffffffffu, rs, off);
            l[i] = l[i] * alpha + rs;
            m[i] = mn;
            #pragma unroll
            for (int j = 0; j < 4; j++) o[i][j] *= alpha;
            Ps[ty * 4 + i][tx * 2 + 0] = p0;
            Ps[ty * 4 + i][tx * 2 + 1] = p1;
        }
        __syncthreads();

        #pragma unroll 8
        for (int kk = 0; kk < 32; kk++) {
            float v0 = Vs[kk][tx * 4 + 0];
            float v1 = Vs[kk][tx * 4 + 1];
            float v2 = Vs[kk][tx * 4 + 2];
            float v3 = Vs[kk][tx * 4 + 3];
            #pragma unroll
            for (int i = 0; i < 4; i++) {
                float p = Ps[ty * 4 + i][kk];
                o[i][0] = fmaf(p, v0, o[i][0]);
                o[i][1] = fmaf(p, v1, o[i][1]);
                o[i][2] = fmaf(p, v2, o[i][2]);
                o[i][3] = fmaf(p, v3, o[i][3]);
            }
        }
    }

    #pragma unroll
    for (int i = 0; i < 4; i++) {
        float inv = 1.0f / l[i];
        int row = qt * 64 + ty * 4 + i;
        float4 ov;
        ov.x = tf32_rna(o[i][0] * inv);
        ov.y = tf32_rna(o[i][1] * inv);
        ov.z = tf32_rna(o[i][2] * inv);
        ov.w = tf32_rna(o[i][3] * inv);
        *(float4*)(y + ((size_t)b * SEQ + row) * EMBED + h * HDIM + tx * 4) = ov;
    }
}

// ---------------- launch ----------------
extern "C" void kernel_launch(void* const* d_in, const int* in_sizes, int n_in,
                              void* d_out, int out_size)
{
    (void)in_sizes; (void)n_in; (void)out_size;
    const float* x      = (const float*)d_in[0];
    const float* ln1_g  = (const float*)d_in[1];
    const float* ln1_b  = (const float*)d_in[2];
    const float* w_qkv  = (const float*)d_in[3];
    const float* b_qkv  = (const float*)d_in[4];
    const float* w_out  = (const float*)d_in[5];
    const float* b_out  = (const float*)d_in[6];
    const float* ln2_g  = (const float*)d_in[7];
    const float* ln2_b  = (const float*)d_in[8];
    const float* w_up   = (const float*)d_in[9];
    const float* b_up   = (const float*)d_in[10];
    const float* w_down = (const float*)d_in[11];
    const float* b_down = (const float*)d_in[12];
    float* out = (float*)d_out;

    float *p_ln, *p_qkv, *p_y, *p_x1, *p_h;
    float *p_wqkvT, *p_woutT, *p_wupT, *p_wdownT;
    cudaGetSymbolAddress((void**)&p_ln,     g_ln);
    cudaGetSymbolAddress((void**)&p_qkv,    g_qkv);
    cudaGetSymbolAddress((void**)&p_y,      g_y);
    cudaGetSymbolAddress((void**)&p_x1,     g_x1);
    cudaGetSymbolAddress((void**)&p_h,      g_h);
    cudaGetSymbolAddress((void**)&p_wqkvT,  g_wqkvT);
    cudaGetSymbolAddress((void**)&p_woutT,  g_woutT);
    cudaGetSymbolAddress((void**)&p_wupT,   g_wupT);
    cudaGetSymbolAddress((void**)&p_wdownT, g_wdownT);

    cudaFuncSetAttribute(gemm_mma<false, false, false>,
                         cudaFuncAttributeMaxDynamicSharedMemorySize, SMEM_DYN);
    cudaFuncSetAttribute(gemm_mma<false, true, false>,
                         cudaFuncAttributeMaxDynamicSharedMemorySize, SMEM_DYN);
    cudaFuncSetAttribute(gemm_mma<true, false, true>,
                         cudaFuncAttributeMaxDynamicSharedMemorySize, SMEM_DYN);

    dim3 tb(32, 8);
    // 0) transpose + tf32-round weights
    transpose_rna<<<dim3(QKV3 / 32, EMBED / 32),  tb>>>(w_qkv,  p_wqkvT,  EMBED, QKV3);
    transpose_rna<<<dim3(EMBED / 32, EMBED / 32), tb>>>(w_out,  p_woutT,  EMBED, EMBED);
    transpose_rna<<<dim3(HIDDEN / 32, EMBED / 32),tb>>>(w_up,   p_wupT,   EMBED, HIDDEN);
    transpose_rna<<<dim3(EMBED / 32, HIDDEN / 32),tb>>>(w_down, p_wdownT, HIDDEN, EMBED);

    // 1) ln1 (tf32-rounded)
    ln_kernel<<<NTOK, 256>>>(x, ln1_g, ln1_b, p_ln);
    // 2) qkv = ln1 @ w_qkv + b_qkv (fp32 out; feeds fp32 attention)
    gemm_mma<false, false, false><<<dim3(QKV3 / BN, NTOK / BM), 256, SMEM_DYN>>>(
        p_ln, p_wqkvT, b_qkv, nullptr, p_qkv, QKV3, EMBED);
    // 3) attention (y tf32-rounded)
    attn_kernel<<<dim3(SEQ / 64, HEADS, BATCH), 256>>>(p_qkv, p_y);
    // 4) x1 = x + y @ w_out + b_out
    gemm_mma<false, true, false><<<dim3(EMBED / BN, NTOK / BM), 256, SMEM_DYN>>>(
        p_y, p_woutT, b_out, x, p_x1, EMBED, EMBED);
    // 5) ln2 (tf32-rounded)
    ln_kernel<<<NTOK, 256>>>(p_x1, ln2_g, ln2_b, p_ln);
    // 6) h = round(relu(ln2 @ w_up + b_up))
    gemm_mma<true, false, true><<<dim3(HIDDEN / BN, NTOK / BM), 256, SMEM_DYN>>>(
        p_ln, p_wupT, b_up, nullptr, p_h, HIDDEN, EMBED);
    // 7) out = x1 + h @ w_down + b_down
    gemm_mma<false, true, false><<<dim3(EMBED / BN, NTOK / BM), 256, SMEM_DYN>>>(
        p_h, p_wdownT, b_down, p_x1, out, EMBED, HIDDEN);
}

// round 4
// speedup vs baseline: 3.4473x; 1.5000x over previous
#include <cuda_runtime.h>
#include <cstdint>
#include <math.h>

#define EMBED   1024
#define SEQ     1024
#define BATCH   8
#define NTOK    8192
#define HIDDEN  4096
#define HEADS   16
#define HDIM    64
#define QKV3    3072

// ---------------- scratch (no cudaMalloc allowed) ----------------
__device__ float g_ln    [NTOK * EMBED];
__device__ float g_qkv   [(size_t)NTOK * QKV3];
__device__ float g_y     [NTOK * EMBED];
__device__ float g_x1    [NTOK * EMBED];
__device__ float g_h     [(size_t)NTOK * HIDDEN];
__device__ float g_wqkvT [(size_t)QKV3 * EMBED];
__device__ float g_woutT [(size_t)EMBED * EMBED];
__device__ float g_wupT  [(size_t)HIDDEN * EMBED];
__device__ float g_wdownT[(size_t)EMBED * HIDDEN];

// ---------------- helpers ----------------
__device__ __forceinline__ uint32_t smem_u32(const void* p) {
    uint32_t a;
    asm("{ .reg .u64 t; cvta.to.shared.u64 t, %1; cvt.u32.u64 %0, t; }" : "=r"(a) : "l"(p));
    return a;
}
__device__ __forceinline__ float tf32_rna(float x) {
    uint32_t u;
    asm("cvt.rna.tf32.f32 %0, %1;" : "=r"(u) : "f"(x));
    return __uint_as_float(u);
}
__device__ __forceinline__ void cp_async16(uint32_t dst, const void* src) {
    asm volatile("cp.async.cg.shared.global [%0], [%1], 16;" :: "r"(dst), "l"(src) : "memory");
}
#define CP_COMMIT() asm volatile("cp.async.commit_group;" ::: "memory")
template <int N>
__device__ __forceinline__ void cp_wait() {
    asm volatile("cp.async.wait_group %0;" :: "n"(N) : "memory");
}

// m16n8k8 tf32 mma (sm_80+ portable PTX)
__device__ __forceinline__ void mma_tf32(float* c, const uint32_t* a, const uint32_t* b) {
    asm volatile(
        "mma.sync.aligned.m16n8k8.row.col.f32.tf32.tf32.f32 "
        "{%0,%1,%2,%3}, {%4,%5,%6,%7}, {%8,%9}, {%0,%1,%2,%3};"
        : "+f"(c[0]), "+f"(c[1]), "+f"(c[2]), "+f"(c[3])
        : "r"(a[0]), "r"(a[1]), "r"(a[2]), "r"(a[3]), "r"(b[0]), "r"(b[1]));
}

// ---------------- tf32 tensor-core GEMM ----------------
// C[M,N] = A[M,K] @ Bt[N,K]^T (+bias)(+res)(relu)(round)
// CTA tile 128M x 256N x 32K, 8 warps (2x4) each 64x64, 3-stage cp.async.
#define BM 128
#define BN 256
#define BK 32
#define PITCH 36                 // 36 mod 32 = 4 -> conflict-free fragment LDS
#define A_F   (BM * PITCH)
#define B_F   (BN * PITCH)
#define STAGE_F (A_F + B_F)
#define NSTAGE 3
#define SMEM_DYN (NSTAGE * STAGE_F * 4)   // 165888 bytes

template<bool RELU, bool RES, bool ROUND>
__global__ void __launch_bounds__(256, 1)
gemm_mma(const float* __restrict__ A, const float* __restrict__ Bt,
         const float* __restrict__ bias, const float* __restrict__ res,
         float* __restrict__ C, int N, int K)
{
    extern __shared__ float sm[];
    const uint32_t sbase = smem_u32(sm);
    const int tid  = threadIdx.x;
    const int wid  = tid >> 5, lane = tid & 31;
    const int gq   = lane >> 2, tq = lane & 3;
    const int wm   = wid >> 2,  wn = wid & 3;
    const int m0   = blockIdx.y * BM, n0 = blockIdx.x * BN;
    const int nk   = K / BK;

    float acc[4][8][4];
    #pragma unroll
    for (int i = 0; i < 4; i++)
        #pragma unroll
        for (int j = 0; j < 8; j++)
            #pragma unroll
            for (int q = 0; q < 4; q++) acc[i][j][q] = 0.f;

    const float* Ag0 = A  + (size_t)m0 * K;
    const float* Bg0 = Bt + (size_t)n0 * K;

    auto load_stage = [&](int s, int kt) {
        uint32_t sa = sbase + (uint32_t)s * (STAGE_F * 4);
        const float* Ag = Ag0 + kt * BK;
        #pragma unroll
        for (int j = 0; j < 4; j++) {
            int c = tid + j * 256;
            int row = c >> 3, kc = c & 7;
            cp_async16(sa + (uint32_t)(row * PITCH + kc * 4) * 4,
                       Ag + (size_t)row * K + kc * 4);
        }
        uint32_t sb = sa + A_F * 4;
        const float* Bg = Bg0 + kt * BK;
        #pragma unroll
        for (int j = 0; j < 8; j++) {
            int c = tid + j * 256;
            int row = c >> 3, kc = c & 7;
            cp_async16(sb + (uint32_t)(row * PITCH + kc * 4) * 4,
                       Bg + (size_t)row * K + kc * 4);
        }
        CP_COMMIT();
    };

    load_stage(0, 0);
    load_stage(1, 1);

    for (int kt = 0; kt < nk; kt++) {
        if (kt + 1 < nk) cp_wait<1>(); else cp_wait<0>();
        __syncthreads();
        if (kt + 2 < nk) load_stage((kt + 2) % NSTAGE, kt + 2);

        const uint32_t* a_s = (const uint32_t*)(sm + (kt % NSTAGE) * STAGE_F);
        const uint32_t* b_s = a_s + A_F;

        #pragma unroll
        for (int ks = 0; ks < 4; ks++) {
            const int k8 = ks * 8;
            uint32_t af[4][4];
            #pragma unroll
            for (int mi = 0; mi < 4; mi++) {
                int rb = wm * 64 + mi * 16;
                af[mi][0] = a_s[(rb + gq)     * PITCH + k8 + tq];
                af[mi][1] = a_s[(rb + gq + 8) * PITCH + k8 + tq];
                af[mi][2] = a_s[(rb + gq)     * PITCH + k8 + tq + 4];
                af[mi][3] = a_s[(rb + gq + 8) * PITCH + k8 + tq + 4];
            }
            uint32_t bf[8][2];
            #pragma unroll
            for (int ni = 0; ni < 8; ni++) {
                int nb = wn * 64 + ni * 8;
                bf[ni][0] = b_s[(nb + gq) * PITCH + k8 + tq];
                bf[ni][1] = b_s[(nb + gq) * PITCH + k8 + tq + 4];
            }
            #pragma unroll
            for (int mi = 0; mi < 4; mi++)
                #pragma unroll
                for (int ni = 0; ni < 8; ni++)
                    mma_tf32(acc[mi][ni], af[mi], bf[ni]);
        }
        __syncthreads();
    }

    // ---------- epilogue ----------
    #pragma unroll
    for (int ni = 0; ni < 8; ni++) {
        int col = n0 + wn * 64 + ni * 8 + 2 * tq;
        float2 bv = __ldg((const float2*)(bias + col));
        #pragma unroll
        for (int mi = 0; mi < 4; mi++) {
            int row = m0 + wm * 64 + mi * 16 + gq;
            float* c0p = C + (size_t)row * N + col;
            float* c1p = C + (size_t)(row + 8) * N + col;
            float2 v0, v1;
            v0.x = acc[mi][ni][0] + bv.x;
            v0.y = acc[mi][ni][1] + bv.y;
            v1.x = acc[mi][ni][2] + bv.x;
            v1.y = acc[mi][ni][3] + bv.y;
            if (RES) {
                float2 r0 = __ldg((const float2*)(res + (size_t)row * N + col));
                float2 r1 = __ldg((const float2*)(res + (size_t)(row + 8) * N + col));
                v0.x += r0.x; v0.y += r0.y;
                v1.x += r1.x; v1.y += r1.y;
            }
            if (RELU) {
                v0.x = fmaxf(v0.x, 0.f); v0.y = fmaxf(v0.y, 0.f);
                v1.x = fmaxf(v1.x, 0.f); v1.y = fmaxf(v1.y, 0.f);
            }
            if (ROUND) {
                v0.x = tf32_rna(v0.x); v0.y = tf32_rna(v0.y);
                v1.x = tf32_rna(v1.x); v1.y = tf32_rna(v1.y);
            }
            *(float2*)c0p = v0;
            *(float2*)c1p = v1;
        }
    }
}

// ---------------- weight transpose + tf32 round: in[K,N] -> out[N,K] ------
__global__ void transpose_rna(const float* __restrict__ in, float* __restrict__ out,
                              int K, int N)
{
    __shared__ float t[32][33];
    int n  = blockIdx.x * 32 + threadIdx.x;
    int k0 = blockIdx.y * 32;
    #pragma unroll
    for (int r = 0; r < 32; r += 8)
        t[threadIdx.y + r][threadIdx.x] = in[(size_t)(k0 + threadIdx.y + r) * N + n];
    __syncthreads();
    int k   = k0 + threadIdx.x;
    int nn0 = blockIdx.x * 32;
    #pragma unroll
    for (int r = 0; r < 32; r += 8)
        out[(size_t)(nn0 + threadIdx.y + r) * K + k] = tf32_rna(t[threadIdx.x][threadIdx.y + r]);
}

// ---------------- LayerNorm (tf32-rounded output; feeds GEMMs only) ------
__global__ void ln_kernel(const float* __restrict__ x,
                          const float* __restrict__ g,
                          const float* __restrict__ b,
                          float* __restrict__ out)
{
    int row = blockIdx.x;
    int t   = threadIdx.x;
    const float4* xr = (const float4*)(x + (size_t)row * EMBED);
    float4 v = xr[t];

    float s  = v.x + v.y + v.z + v.w;
    float s2 = v.x*v.x + v.y*v.y + v.z*v.z + v.w*v.w;
    #pragma unroll
    for (int off = 16; off > 0; off >>= 1) {
        s  += __shfl_xor_sync(0xffffffffu, s,  off);
        s2 += __shfl_xor_sync(0xffffffffu, s2, off);
    }
    __shared__ float red1[8], red2[8];
    int wid = t >> 5, lane = t & 31;
    if (lane == 0) { red1[wid] = s; red2[wid] = s2; }
    __syncthreads();
    __shared__ float s_mu, s_rstd;
    if (t == 0) {
        float ts = 0.f, ts2 = 0.f;
        #pragma unroll
        for (int i = 0; i < 8; i++) { ts += red1[i]; ts2 += red2[i]; }
        float mu  = ts * (1.0f / EMBED);
        float var = ts2 * (1.0f / EMBED) - mu * mu;
        s_mu = mu; s_rstd = rsqrtf(var + 1e-5f);
    }
    __syncthreads();
    float mu = s_mu, rstd = s_rstd;

    float4 gv = ((const float4*)g)[t];
    float4 bv = ((const float4*)b)[t];
    float4 o;
    o.x = tf32_rna((v.x - mu) * rstd * gv.x + bv.x);
    o.y = tf32_rna((v.y - mu) * rstd * gv.y + bv.y);
    o.z = tf32_rna((v.z - mu) * rstd * gv.z + bv.z);
    o.w = tf32_rna((v.w - mu) * rstd * gv.w + bv.w);
    ((float4*)(out + (size_t)row * EMBED))[t] = o;
}

// ---------------- flash attention via mma.sync tf32 ----------------
// BQ=128 per CTA, 4 warps (32 q-rows each: 2 x m16), BK=64, D=64.
// qkv values are already tf32-rounded (qkv GEMM epilogue ROUND).
#define ATT_P 72     // smem pitch (floats); banks gq*8+tq / tq*8+gq all distinct
#define ATT_SMEM ((128 + 64 + 64 + 128) * ATT_P * 4)   // 110592 bytes

__global__ void __launch_bounds__(128, 2)
attn_mma(const float* __restrict__ qkv, float* __restrict__ y)
{
    extern __shared__ float sm[];
    float* Qs = sm;                      // [128][ATT_P]
    float* Ks = Qs + 128 * ATT_P;        // [64][ATT_P]  (kv rows, d cols)
    float* Vs = Ks + 64 * ATT_P;         // [64][ATT_P]  (kv rows, d cols)
    float* Ps = Vs + 64 * ATT_P;         // [128][ATT_P] (q rows, kv cols)
    const uint32_t sb = smem_u32(sm);
    const uint32_t Qb = sb;
    const uint32_t Kb = sb + 128 * ATT_P * 4;
    const uint32_t Vb = Kb + 64 * ATT_P * 4;

    const int qt = blockIdx.x, h = blockIdx.y, b = blockIdx.z;
    const int tid = threadIdx.x, wid = tid >> 5, lane = tid & 31;
    const int gq = lane >> 2, tq = lane & 3;

    // load Q tile (128 x 64) via cp.async
    const float* qbase = qkv + ((size_t)b * SEQ + qt * 128) * QKV3 + h * HDIM;
    #pragma unroll
    for (int j = 0; j < 16; j++) {
        int c = tid + j * 128;           // 0..2047
        int row = c >> 4, cc = c & 15;
        cp_async16(Qb + (uint32_t)(row * ATT_P + cc * 4) * 4,
                   qbase + (size_t)row * QKV3 + cc * 4);
    }
    CP_COMMIT();

    float o[2][8][4];
    float mrow[2][2], lrow[2][2];
    #pragma unroll
    for (int mi = 0; mi < 2; mi++) {
        mrow[mi][0] = mrow[mi][1] = -1e30f;
        lrow[mi][0] = lrow[mi][1] = 0.f;
        #pragma unroll
        for (int ni = 0; ni < 8; ni++)
            #pragma unroll
            for (int q = 0; q < 4; q++) o[mi][ni][q] = 0.f;
    }

    const float* kbase = qkv + (size_t)b * SEQ * QKV3 + EMBED + h * HDIM;
    const float* vbase = kbase + EMBED;
    const int rb0 = wid * 32;            // warp's q-row base

    for (int kt = 0; kt < SEQ / 64; kt++) {
        // load K,V tiles (single buffer)
        #pragma unroll
        for (int j = 0; j < 8; j++) {
            int c = tid + j * 128;       // 0..1023
            int row = c >> 4, cc = c & 15;
            size_t goff = (size_t)(kt * 64 + row) * QKV3 + cc * 4;
            uint32_t soff = (uint32_t)(row * ATT_P + cc * 4) * 4;
            cp_async16(Kb + soff, kbase + goff);
            cp_async16(Vb + soff, vbase + goff);
        }
        CP_COMMIT();
        cp_wait<0>();
        __syncthreads();

        // ---- S = Q @ K^T  (M=32/warp, N=64, K=64) ----
        float s[2][8][4];
        #pragma unroll
        for (int mi = 0; mi < 2; mi++)
            #pragma unroll
            for (int ni = 0; ni < 8; ni++)
                #pragma unroll
                for (int q = 0; q < 4; q++) s[mi][ni][q] = 0.f;

        #pragma unroll
        for (int ks = 0; ks < 8; ks++) {
            const int k8 = ks * 8;
            uint32_t aq[2][4];
            #pragma unroll
            for (int mi = 0; mi < 2; mi++) {
                int rb = rb0 + mi * 16;
                const uint32_t* q_s = (const uint32_t*)Qs;
                aq[mi][0] = q_s[(rb + gq)     * ATT_P + k8 + tq];
                aq[mi][1] = q_s[(rb + gq + 8) * ATT_P + k8 + tq];
                aq[mi][2] = q_s[(rb + gq)     * ATT_P + k8 + tq + 4];
                aq[mi][3] = q_s[(rb + gq + 8) * ATT_P + k8 + tq + 4];
            }
            uint32_t bk[8][2];
            const uint32_t* k_s = (const uint32_t*)Ks;
            #pragma unroll
            for (int ni = 0; ni < 8; ni++) {
                bk[ni][0] = k_s[(ni * 8 + gq) * ATT_P + k8 + tq];
                bk[ni][1] = k_s[(ni * 8 + gq) * ATT_P + k8 + tq + 4];
            }
            #pragma unroll
            for (int mi = 0; mi < 2; mi++)
                #pragma unroll
                for (int ni = 0; ni < 8; ni++)
                    mma_tf32(s[mi][ni], aq[mi], bk[ni]);
        }

        // ---- online softmax on fragments ----
        #pragma unroll
        for (int mi = 0; mi < 2; mi++) {
            float rm0 = -1e30f, rm1 = -1e30f;
            #pragma unroll
            for (int ni = 0; ni < 8; ni++) {
                #pragma unroll
                for (int q = 0; q < 4; q++) s[mi][ni][q] *= 0.125f;
                rm0 = fmaxf(rm0, fmaxf(s[mi][ni][0], s[mi][ni][1]));
                rm1 = fmaxf(rm1, fmaxf(s[mi][ni][2], s[mi][ni][3]));
            }
            rm0 = fmaxf(rm0, __shfl_xor_sync(0xffffffffu, rm0, 1));
            rm0 = fmaxf(rm0, __shfl_xor_sync(0xffffffffu, rm0, 2));
            rm1 = fmaxf(rm1, __shfl_xor_sync(0xffffffffu, rm1, 1));
            rm1 = fmaxf(rm1, __shfl_xor_sync(0xffffffffu, rm1, 2));

            float mn0 = fmaxf(mrow[mi][0], rm0);
            float mn1 = fmaxf(mrow[mi][1], rm1);
            float a0 = __expf(mrow[mi][0] - mn0);
            float a1 = __expf(mrow[mi][1] - mn1);
            mrow[mi][0] = mn0; mrow[mi][1] = mn1;

            float sum0 = 0.f, sum1 = 0.f;
            int rb = rb0 + mi * 16;
            float* prow0 = Ps + (rb + gq) * ATT_P + 2 * tq;
            float* prow1 = Ps + (rb + gq + 8) * ATT_P + 2 * tq;
            #pragma unroll
            for (int ni = 0; ni < 8; ni++) {
                float p0 = __expf(s[mi][ni][0] - mn0);
                float p1 = __expf(s[mi][ni][1] - mn0);
                float p2 = __expf(s[mi][ni][2] - mn1);
                float p3 = __expf(s[mi][ni][3] - mn1);
                sum0 += p0 + p1;
                sum1 += p2 + p3;
                float2 w0 = make_float2(tf32_rna(p0), tf32_rna(p1));
                float2 w1 = make_float2(tf32_rna(p2), tf32_rna(p3));
                *(float2*)(prow0 + ni * 8) = w0;
                *(float2*)(prow1 + ni * 8) = w1;
                // rescale O by alpha
                o[mi][ni][0] *= a0; o[mi][ni][1] *= a0;
                o[mi][ni][2] *= a1; o[mi][ni][3] *= a1;
            }
            sum0 += __shfl_xor_sync(0xffffffffu, sum0, 1);
            sum0 += __shfl_xor_sync(0xffffffffu, sum0, 2);
            sum1 += __shfl_xor_sync(0xffffffffu, sum1, 1);
            sum1 += __shfl_xor_sync(0xffffffffu, sum1, 2);
            lrow[mi][0] = lrow[mi][0] * a0 + sum0;
            lrow[mi][1] = lrow[mi][1] * a1 + sum1;
        }
        __syncwarp();

        // ---- O += P @ V  (A = P[q][kv], B = V^T[d][kv] read from V[kv][d]) ----
        #pragma unroll
        for (int ks = 0; ks < 8; ks++) {
            const int k8 = ks * 8;
            uint32_t ap[2][4];
            const uint32_t* p_s = (const uint32_t*)Ps;
            #pragma unroll
            for (int mi = 0; mi < 2; mi++) {
                int rb = rb0 + mi * 16;
                ap[mi][0] = p_s[(rb + gq)     * ATT_P + k8 + tq];
                ap[mi][1] = p_s[(rb + gq + 8) * ATT_P + k8 + tq];
                ap[mi][2] = p_s[(rb + gq)     * ATT_P + k8 + tq + 4];
                ap[mi][3] = p_s[(rb + gq + 8) * ATT_P + k8 + tq + 4];
            }
            uint32_t bv[8][2];
            const uint32_t* v_s = (const uint32_t*)Vs;
            #pragma unroll
            for (int ni = 0; ni < 8; ni++) {
                bv[ni][0] = v_s[(k8 + tq)     * ATT_P + ni * 8 + gq];
                bv[ni][1] = v_s[(k8 + tq + 4) * ATT_P + ni * 8 + gq];
            }
            #pragma unroll
            for (int mi = 0; mi < 2; mi++)
                #pragma unroll
                for (int ni = 0; ni < 8; ni++)
                    mma_tf32(o[mi][ni], ap[mi], bv[ni]);
        }
        __syncthreads();   // protect K/V before next overwrite
    }

    // ---- write y (tf32-rounded; feeds out-proj GEMM) ----
    #pragma unroll
    for (int mi = 0; mi < 2; mi++) {
        float inv0 = 1.0f / lrow[mi][0];
        float inv1 = 1.0f / lrow[mi][1];
        int r0 = qt * 128 + rb0 + mi * 16 + gq;
        #pragma unroll
        for (int ni = 0; ni < 8; ni++) {
            int col = h * HDIM + ni * 8 + 2 * tq;
            float2 w0, w1;
            w0.x = tf32_rna(o[mi][ni][0] * inv0);
            w0.y = tf32_rna(o[mi][ni][1] * inv0);
            w1.x = tf32_rna(o[mi][ni][2] * inv1);
            w1.y = tf32_rna(o[mi][ni][3] * inv1);
            *(float2*)(y + ((size_t)b * SEQ + r0) * EMBED + col) = w0;
            *(float2*)(y + ((size_t)b * SEQ + r0 + 8) * EMBED + col) = w1;
        }
    }
}

// ---------------- launch ----------------
extern "C" void kernel_launch(void* const* d_in, const int* in_sizes, int n_in,
                              void* d_out, int out_size)
{
    (void)in_sizes; (void)n_in; (void)out_size;
    const float* x      = (const float*)d_in[0];
    const float* ln1_g  = (const float*)d_in[1];
    const float* ln1_b  = (const float*)d_in[2];
    const float* w_qkv  = (const float*)d_in[3];
    const float* b_qkv  = (const float*)d_in[4];
    const float* w_out  = (const float*)d_in[5];
    const float* b_out  = (const float*)d_in[6];
    const float* ln2_g  = (const float*)d_in[7];
    const float* ln2_b  = (const float*)d_in[8];
    const float* w_up   = (const float*)d_in[9];
    const float* b_up   = (const float*)d_in[10];
    const float* w_down = (const float*)d_in[11];
    const float* b_down = (const float*)d_in[12];
    float* out = (float*)d_out;

    float *p_ln, *p_qkv, *p_y, *p_x1, *p_h;
    float *p_wqkvT, *p_woutT, *p_wupT, *p_wdownT;
    cudaGetSymbolAddress((void**)&p_ln,     g_ln);
    cudaGetSymbolAddress((void**)&p_qkv,    g_qkv);
    cudaGetSymbolAddress((void**)&p_y,      g_y);
    cudaGetSymbolAddress((void**)&p_x1,     g_x1);
    cudaGetSymbolAddress((void**)&p_h,      g_h);
    cudaGetSymbolAddress((void**)&p_wqkvT,  g_wqkvT);
    cudaGetSymbolAddress((void**)&p_woutT,  g_woutT);
    cudaGetSymbolAddress((void**)&p_wupT,   g_wupT);
    cudaGetSymbolAddress((void**)&p_wdownT, g_wdownT);

    cudaFuncSetAttribute(gemm_mma<false, false, true>,
                         cudaFuncAttributeMaxDynamicSharedMemorySize, SMEM_DYN);
    cudaFuncSetAttribute(gemm_mma<false, true, false>,
                         cudaFuncAttributeMaxDynamicSharedMemorySize, SMEM_DYN);
    cudaFuncSetAttribute(gemm_mma<true, false, true>,
                         cudaFuncAttributeMaxDynamicSharedMemorySize, SMEM_DYN);
    cudaFuncSetAttribute(attn_mma,
                         cudaFuncAttributeMaxDynamicSharedMemorySize, ATT_SMEM);

    dim3 tb(32, 8);
    // 0) transpose + tf32-round weights
    transpose_rna<<<dim3(QKV3 / 32, EMBED / 32),  tb>>>(w_qkv,  p_wqkvT,  EMBED, QKV3);
    transpose_rna<<<dim3(EMBED / 32, EMBED / 32), tb>>>(w_out,  p_woutT,  EMBED, EMBED);
    transpose_rna<<<dim3(HIDDEN / 32, EMBED / 32),tb>>>(w_up,   p_wupT,   EMBED, HIDDEN);
    transpose_rna<<<dim3(EMBED / 32, HIDDEN / 32),tb>>>(w_down, p_wdownT, HIDDEN, EMBED);

    // 1) ln1 (tf32-rounded)
    ln_kernel<<<NTOK, 256>>>(x, ln1_g, ln1_b, p_ln);
    // 2) qkv = ln1 @ w_qkv + b_qkv (tf32-rounded: feeds mma attention)
    gemm_mma<false, false, true><<<dim3(QKV3 / BN, NTOK / BM), 256, SMEM_DYN>>>(
        p_ln, p_wqkvT, b_qkv, nullptr, p_qkv, QKV3, EMBED);
    // 3) attention (tensor cores; y tf32-rounded)
    attn_mma<<<dim3(SEQ / 128, HEADS, BATCH), 128, ATT_SMEM>>>(p_qkv, p_y);
    // 4) x1 = x + y @ w_out + b_out
    gemm_mma<false, true, false><<<dim3(EMBED / BN, NTOK / BM), 256, SMEM_DYN>>>(
        p_y, p_woutT, b_out, x, p_x1, EMBED, EMBED);
    // 5) ln2 (tf32-rounded)
    ln_kernel<<<NTOK, 256>>>(p_x1, ln2_g, ln2_b, p_ln);
    // 6) h = round(relu(ln2 @ w_up + b_up))
    gemm_mma<true, false, true><<<dim3(HIDDEN / BN, NTOK / BM), 256, SMEM_DYN>>>(
        p_ln, p_wupT, b_up, nullptr, p_h, HIDDEN, EMBED);
    // 7) out = x1 + h @ w_down + b_down
    gemm_mma<false, true, false><<<dim3(EMBED / BN, NTOK / BM), 256, SMEM_DYN>>>(
        p_h, p_wdownT, b_down, p_x1, out, EMBED, HIDDEN);
}

// round 5
// speedup vs baseline: 3.4504x; 1.0009x over previous
#include <cuda_runtime.h>
#include <cstdint>
#include <math.h>

#define EMBED   1024
#define SEQ     1024
#define BATCH   8
#define NTOK    8192
#define HIDDEN  4096
#define HEADS   16
#define HDIM    64
#define QKV3    3072

// ---------------- scratch (no cudaMalloc allowed) ----------------
__device__ float g_ln    [NTOK * EMBED];
__device__ float g_qkv   [(size_t)NTOK * QKV3];
__device__ float g_y     [NTOK * EMBED];
__device__ float g_x1    [NTOK * EMBED];
__device__ float g_h     [(size_t)NTOK * HIDDEN];
__device__ float g_wqkvT [(size_t)QKV3 * EMBED];
__device__ float g_woutT [(size_t)EMBED * EMBED];
__device__ float g_wupT  [(size_t)HIDDEN * EMBED];
__device__ float g_wdownT[(size_t)EMBED * HIDDEN];

// ---------------- helpers ----------------
__device__ __forceinline__ uint32_t smem_u32(const void* p) {
    uint32_t a;
    asm("{ .reg .u64 t; cvta.to.shared.u64 t, %1; cvt.u32.u64 %0, t; }" : "=r"(a) : "l"(p));
    return a;
}
__device__ __forceinline__ float tf32_rna(float x) {
    uint32_t u;
    asm("cvt.rna.tf32.f32 %0, %1;" : "=r"(u) : "f"(x));
    return __uint_as_float(u);
}
__device__ __forceinline__ void cp_async16(uint32_t dst, const void* src) {
    asm volatile("cp.async.cg.shared.global [%0], [%1], 16;" :: "r"(dst), "l"(src) : "memory");
}
#define CP_COMMIT() asm volatile("cp.async.commit_group;" ::: "memory")
template <int N>
__device__ __forceinline__ void cp_wait() {
    asm volatile("cp.async.wait_group %0;" :: "n"(N) : "memory");
}

// m16n8k8 tf32 mma (sm_80+ portable PTX)
__device__ __forceinline__ void mma_tf32(float* c, const uint32_t* a, const uint32_t* b) {
    asm volatile(
        "mma.sync.aligned.m16n8k8.row.col.f32.tf32.tf32.f32 "
        "{%0,%1,%2,%3}, {%4,%5,%6,%7}, {%8,%9}, {%0,%1,%2,%3};"
        : "+f"(c[0]), "+f"(c[1]), "+f"(c[2]), "+f"(c[3])
        : "r"(a[0]), "r"(a[1]), "r"(a[2]), "r"(a[3]), "r"(b[0]), "r"(b[1]));
}

// ---------------- tf32 tensor-core GEMM ----------------
// C[M,N] = A[M,K] @ Bt[N,K]^T (+bias)(+res)(relu)(round)
// CTA tile 128M x 256N x 32K, 8 warps (2x4) each 64x64,
// 4-stage cp.async pipeline + register double-buffered fragments.
#define BM 128
#define BN 256
#define BK 32
#define PITCH 36                 // 36 mod 32 = 4 -> conflict-free fragment LDS
#define A_F   (BM * PITCH)
#define B_F   (BN * PITCH)
#define STAGE_F (A_F + B_F)
#define NSTAGE 4
#define SMEM_DYN (NSTAGE * STAGE_F * 4)   // 221184 bytes

template<bool RELU, bool RES, bool ROUND>
__global__ void __launch_bounds__(256, 1)
gemm_mma(const float* __restrict__ A, const float* __restrict__ Bt,
         const float* __restrict__ bias, const float* __restrict__ res,
         float* __restrict__ C, int N, int K)
{
    extern __shared__ float sm[];
    const uint32_t sbase = smem_u32(sm);
    const int tid  = threadIdx.x;
    const int wid  = tid >> 5, lane = tid & 31;
    const int gq   = lane >> 2, tq = lane & 3;
    const int wm   = wid >> 2,  wn = wid & 3;
    const int m0   = blockIdx.y * BM, n0 = blockIdx.x * BN;
    const int nk   = K / BK;

    float acc[4][8][4];
    #pragma unroll
    for (int i = 0; i < 4; i++)
        #pragma unroll
        for (int j = 0; j < 8; j++)
            #pragma unroll
            for (int q = 0; q < 4; q++) acc[i][j][q] = 0.f;

    const float* Ag0 = A  + (size_t)m0 * K;
    const float* Bg0 = Bt + (size_t)n0 * K;

    auto load_stage = [&](int s, int kt) {
        uint32_t sa = sbase + (uint32_t)s * (STAGE_F * 4);
        const float* Ag = Ag0 + kt * BK;
        #pragma unroll
        for (int j = 0; j < 4; j++) {
            int c = tid + j * 256;
            int row = c >> 3, kc = c & 7;
            cp_async16(sa + (uint32_t)(row * PITCH + kc * 4) * 4,
                       Ag + (size_t)row * K + kc * 4);
        }
        uint32_t sb = sa + A_F * 4;
        const float* Bg = Bg0 + kt * BK;
        #pragma unroll
        for (int j = 0; j < 8; j++) {
            int c = tid + j * 256;
            int row = c >> 3, kc = c & 7;
            cp_async16(sb + (uint32_t)(row * PITCH + kc * 4) * 4,
                       Bg + (size_t)row * K + kc * 4);
        }
        CP_COMMIT();
    };

    load_stage(0, 0);
    load_stage(1, 1);
    load_stage(2, 2);

    for (int kt = 0; kt < nk; kt++) {
        if (kt + 2 < nk) cp_wait<2>();
        else if (kt + 1 < nk) cp_wait<1>();
        else cp_wait<0>();
        __syncthreads();
        if (kt + 3 < nk) load_stage((kt + 3) % NSTAGE, kt + 3);

        const uint32_t* a_s = (const uint32_t*)(sm + (kt % NSTAGE) * STAGE_F);
        const uint32_t* b_s = a_s + A_F;

        uint32_t af[2][4][4], bf[2][8][2];

        auto ld_frags = [&](int ks, int bufi) {
            const int k8 = ks * 8;
            #pragma unroll
            for (int mi = 0; mi < 4; mi++) {
                int rb = wm * 64 + mi * 16;
                af[bufi][mi][0] = a_s[(rb + gq)     * PITCH + k8 + tq];
                af[bufi][mi][1] = a_s[(rb + gq + 8) * PITCH + k8 + tq];
                af[bufi][mi][2] = a_s[(rb + gq)     * PITCH + k8 + tq + 4];
                af[bufi][mi][3] = a_s[(rb + gq + 8) * PITCH + k8 + tq + 4];
            }
            #pragma unroll
            for (int ni = 0; ni < 8; ni++) {
                int nb = wn * 64 + ni * 8;
                bf[bufi][ni][0] = b_s[(nb + gq) * PITCH + k8 + tq];
                bf[bufi][ni][1] = b_s[(nb + gq) * PITCH + k8 + tq + 4];
            }
        };

        ld_frags(0, 0);
        #pragma unroll
        for (int ks = 0; ks < 4; ks++) {
            const int cu = ks & 1;
            if (ks < 3) ld_frags(ks + 1, cu ^ 1);
            #pragma unroll
            for (int mi = 0; mi < 4; mi++)
                #pragma unroll
                for (int ni = 0; ni < 8; ni++)
                    mma_tf32(acc[mi][ni], af[cu][mi], bf[cu][ni]);
        }
        __syncthreads();
    }

    // ---------- epilogue ----------
    #pragma unroll
    for (int ni = 0; ni < 8; ni++) {
        int col = n0 + wn * 64 + ni * 8 + 2 * tq;
        float2 bv = __ldg((const float2*)(bias + col));
        #pragma unroll
        for (int mi = 0; mi < 4; mi++) {
            int row = m0 + wm * 64 + mi * 16 + gq;
            float* c0p = C + (size_t)row * N + col;
            float* c1p = C + (size_t)(row + 8) * N + col;
            float2 v0, v1;
            v0.x = acc[mi][ni][0] + bv.x;
            v0.y = acc[mi][ni][1] + bv.y;
            v1.x = acc[mi][ni][2] + bv.x;
            v1.y = acc[mi][ni][3] + bv.y;
            if (RES) {
                float2 r0 = __ldg((const float2*)(res + (size_t)row * N + col));
                float2 r1 = __ldg((const float2*)(res + (size_t)(row + 8) * N + col));
                v0.x += r0.x; v0.y += r0.y;
                v1.x += r1.x; v1.y += r1.y;
            }
            if (RELU) {
                v0.x = fmaxf(v0.x, 0.f); v0.y = fmaxf(v0.y, 0.f);
                v1.x = fmaxf(v1.x, 0.f); v1.y = fmaxf(v1.y, 0.f);
            }
            if (ROUND) {
                v0.x = tf32_rna(v0.x); v0.y = tf32_rna(v0.y);
                v1.x = tf32_rna(v1.x); v1.y = tf32_rna(v1.y);
            }
            *(float2*)c0p = v0;
            *(float2*)c1p = v1;
        }
    }
}

// ---------------- weight transpose + tf32 round: in[K,N] -> out[N,K] ------
__global__ void transpose_rna(const float* __restrict__ in, float* __restrict__ out,
                              int K, int N)
{
    __shared__ float t[32][33];
    int n  = blockIdx.x * 32 + threadIdx.x;
    int k0 = blockIdx.y * 32;
    #pragma unroll
    for (int r = 0; r < 32; r += 8)
        t[threadIdx.y + r][threadIdx.x] = in[(size_t)(k0 + threadIdx.y + r) * N + n];
    __syncthreads();
    int k   = k0 + threadIdx.x;
    int nn0 = blockIdx.x * 32;
    #pragma unroll
    for (int r = 0; r < 32; r += 8)
        out[(size_t)(nn0 + threadIdx.y + r) * K + k] = tf32_rna(t[threadIdx.x][threadIdx.y + r]);
}

// ---------------- LayerNorm (tf32-rounded output; feeds GEMMs only) ------
__global__ void ln_kernel(const float* __restrict__ x,
                          const float* __restrict__ g,
                          const float* __restrict__ b,
                          float* __restrict__ out)
{
    int row = blockIdx.x;
    int t   = threadIdx.x;
    const float4* xr = (const float4*)(x + (size_t)row * EMBED);
    float4 v = xr[t];

    float s  = v.x + v.y + v.z + v.w;
    float s2 = v.x*v.x + v.y*v.y + v.z*v.z + v.w*v.w;
    #pragma unroll
    for (int off = 16; off > 0; off >>= 1) {
        s  += __shfl_xor_sync(0xffffffffu, s,  off);
        s2 += __shfl_xor_sync(0xffffffffu, s2, off);
    }
    __shared__ float red1[8], red2[8];
    int wid = t >> 5, lane = t & 31;
    if (lane == 0) { red1[wid] = s; red2[wid] = s2; }
    __syncthreads();
    __shared__ float s_mu, s_rstd;
    if (t == 0) {
        float ts = 0.f, ts2 = 0.f;
        #pragma unroll
        for (int i = 0; i < 8; i++) { ts += red1[i]; ts2 += red2[i]; }
        float mu  = ts * (1.0f / EMBED);
        float var = ts2 * (1.0f / EMBED) - mu * mu;
        s_mu = mu; s_rstd = rsqrtf(var + 1e-5f);
    }
    __syncthreads();
    float mu = s_mu, rstd = s_rstd;

    float4 gv = ((const float4*)g)[t];
    float4 bv = ((const float4*)b)[t];
    float4 o;
    o.x = tf32_rna((v.x - mu) * rstd * gv.x + bv.x);
    o.y = tf32_rna((v.y - mu) * rstd * gv.y + bv.y);
    o.z = tf32_rna((v.z - mu) * rstd * gv.z + bv.z);
    o.w = tf32_rna((v.w - mu) * rstd * gv.w + bv.w);
    ((float4*)(out + (size_t)row * EMBED))[t] = o;
}

// ---------------- flash attention via mma.sync tf32 ----------------
// BQ=128 per CTA, 4 warps (32 q-rows each: 2 x m16), BK=64, D=64.
#define ATT_P 72
#define ATT_SMEM ((128 + 64 + 64 + 128) * ATT_P * 4)   // 110592 bytes

__global__ void __launch_bounds__(128, 2)
attn_mma(const float* __restrict__ qkv, float* __restrict__ y)
{
    extern __shared__ float sm[];
    float* Qs = sm;                      // [128][ATT_P]
    float* Ks = Qs + 128 * ATT_P;        // [64][ATT_P]
    float* Vs = Ks + 64 * ATT_P;         // [64][ATT_P]
    float* Ps = Vs + 64 * ATT_P;         // [128][ATT_P]
    const uint32_t sb = smem_u32(sm);
    const uint32_t Qb = sb;
    const uint32_t Kb = sb + 128 * ATT_P * 4;
    const uint32_t Vb = Kb + 64 * ATT_P * 4;

    const int qt = blockIdx.x, h = blockIdx.y, b = blockIdx.z;
    const int tid = threadIdx.x, wid = tid >> 5, lane = tid & 31;
    const int gq = lane >> 2, tq = lane & 3;

    // load Q tile (128 x 64)
    const float* qbase = qkv + ((size_t)b * SEQ + qt * 128) * QKV3 + h * HDIM;
    #pragma unroll
    for (int j = 0; j < 16; j++) {
        int c = tid + j * 128;
        int row = c >> 4, cc = c & 15;
        cp_async16(Qb + (uint32_t)(row * ATT_P + cc * 4) * 4,
                   qbase + (size_t)row * QKV3 + cc * 4);
    }
    CP_COMMIT();

    float o[2][8][4];
    float mrow[2][2], lrow[2][2];
    #pragma unroll
    for (int mi = 0; mi < 2; mi++) {
        mrow[mi][0] = mrow[mi][1] = -1e30f;
        lrow[mi][0] = lrow[mi][1] = 0.f;
        #pragma unroll
        for (int ni = 0; ni < 8; ni++)
            #pragma unroll
            for (int q = 0; q < 4; q++) o[mi][ni][q] = 0.f;
    }

    const float* kbase = qkv + (size_t)b * SEQ * QKV3 + EMBED + h * HDIM;
    const float* vbase = kbase + EMBED;
    const int rb0 = wid * 32;

    for (int kt = 0; kt < SEQ / 64; kt++) {
        // K group, then V group (separate commits -> overlap V with S)
        #pragma unroll
        for (int j = 0; j < 8; j++) {
            int c = tid + j * 128;
            int row = c >> 4, cc = c & 15;
            cp_async16(Kb + (uint32_t)(row * ATT_P + cc * 4) * 4,
                       kbase + (size_t)(kt * 64 + row) * QKV3 + cc * 4);
        }
        CP_COMMIT();
        #pragma unroll
        for (int j = 0; j < 8; j++) {
            int c = tid + j * 128;
            int row = c >> 4, cc = c & 15;
            cp_async16(Vb + (uint32_t)(row * ATT_P + cc * 4) * 4,
                       vbase + (size_t)(kt * 64 + row) * QKV3 + cc * 4);
        }
        CP_COMMIT();

        cp_wait<1>();          // Q + K ready, V in flight
        __syncthreads();

        // ---- S = Q @ K^T ----
        float s[2][8][4];
        #pragma unroll
        for (int mi = 0; mi < 2; mi++)
            #pragma unroll
            for (int ni = 0; ni < 8; ni++)
                #pragma unroll
                for (int q = 0; q < 4; q++) s[mi][ni][q] = 0.f;

        #pragma unroll
        for (int ks = 0; ks < 8; ks++) {
            const int k8 = ks * 8;
            uint32_t aq[2][4];
            const uint32_t* q_s = (const uint32_t*)Qs;
            #pragma unroll
            for (int mi = 0; mi < 2; mi++) {
                int rb = rb0 + mi * 16;
                aq[mi][0] = q_s[(rb + gq)     * ATT_P + k8 + tq];
                aq[mi][1] = q_s[(rb + gq + 8) * ATT_P + k8 + tq];
                aq[mi][2] = q_s[(rb + gq)     * ATT_P + k8 + tq + 4];
                aq[mi][3] = q_s[(rb + gq + 8) * ATT_P + k8 + tq + 4];
            }
            uint32_t bk[8][2];
            const uint32_t* k_s = (const uint32_t*)Ks;
            #pragma unroll
            for (int ni = 0; ni < 8; ni++) {
                bk[ni][0] = k_s[(ni * 8 + gq) * ATT_P + k8 + tq];
                bk[ni][1] = k_s[(ni * 8 + gq) * ATT_P + k8 + tq + 4];
            }
            #pragma unroll
            for (int mi = 0; mi < 2; mi++)
                #pragma unroll
                for (int ni = 0; ni < 8; ni++)
                    mma_tf32(s[mi][ni], aq[mi], bk[ni]);
        }

        // ---- online softmax ----
        #pragma unroll
        for (int mi = 0; mi < 2; mi++) {
            float rm0 = -1e30f, rm1 = -1e30f;
            #pragma unroll
            for (int ni = 0; ni < 8; ni++) {
                #pragma unroll
                for (int q = 0; q < 4; q++) s[mi][ni][q] *= 0.125f;
                rm0 = fmaxf(rm0, fmaxf(s[mi][ni][0], s[mi][ni][1]));
                rm1 = fmaxf(rm1, fmaxf(s[mi][ni][2], s[mi][ni][3]));
            }
            rm0 = fmaxf(rm0, __shfl_xor_sync(0xffffffffu, rm0, 1));
            rm0 = fmaxf(rm0, __shfl_xor_sync(0xffffffffu, rm0, 2));
            rm1 = fmaxf(rm1, __shfl_xor_sync(0xffffffffu, rm1, 1));
            rm1 = fmaxf(rm1, __shfl_xor_sync(0xffffffffu, rm1, 2));

            float mn0 = fmaxf(mrow[mi][0], rm0);
            float mn1 = fmaxf(mrow[mi][1], rm1);
            float a0 = __expf(mrow[mi][0] - mn0);
            float a1 = __expf(mrow[mi][1] - mn1);
            mrow[mi][0] = mn0; mrow[mi][1] = mn1;

            float sum0 = 0.f, sum1 = 0.f;
            int rb = rb0 + mi * 16;
            float* prow0 = Ps + (rb + gq) * ATT_P + 2 * tq;
            float* prow1 = Ps + (rb + gq + 8) * ATT_P + 2 * tq;
            #pragma unroll
            for (int ni = 0; ni < 8; ni++) {
                float p0 = __expf(s[mi][ni][0] - mn0);
                float p1 = __expf(s[mi][ni][1] - mn0);
                float p2 = __expf(s[mi][ni][2] - mn1);
                float p3 = __expf(s[mi][ni][3] - mn1);
                sum0 += p0 + p1;
                sum1 += p2 + p3;
                *(float2*)(prow0 + ni * 8) = make_float2(tf32_rna(p0), tf32_rna(p1));
                *(float2*)(prow1 + ni * 8) = make_float2(tf32_rna(p2), tf32_rna(p3));
                o[mi][ni][0] *= a0; o[mi][ni][1] *= a0;
                o[mi][ni][2] *= a1; o[mi][ni][3] *= a1;
            }
            sum0 += __shfl_xor_sync(0xffffffffu, sum0, 1);
            sum0 += __shfl_xor_sync(0xffffffffu, sum0, 2);
            sum1 += __shfl_xor_sync(0xffffffffu, sum1, 1);
            sum1 += __shfl_xor_sync(0xffffffffu, sum1, 2);
            lrow[mi][0] = lrow[mi][0] * a0 + sum0;
            lrow[mi][1] = lrow[mi][1] * a1 + sum1;
        }
        __syncwarp();

        cp_wait<0>();          // V ready
        __syncthreads();

        // ---- O += P @ V ----
        #pragma unroll
        for (int ks = 0; ks < 8; ks++) {
            const int k8 = ks * 8;
            uint32_t ap[2][4];
            const uint32_t* p_s = (const uint32_t*)Ps;
            #pragma unroll
            for (int mi = 0; mi < 2; mi++) {
                int rb = rb0 + mi * 16;
                ap[mi][0] = p_s[(rb + gq)     * ATT_P + k8 + tq];
                ap[mi][1] = p_s[(rb + gq + 8) * ATT_P + k8 + tq];
                ap[mi][2] = p_s[(rb + gq)     * ATT_P + k8 + tq + 4];
                ap[mi][3] = p_s[(rb + gq + 8) * ATT_P + k8 + tq + 4];
            }
            uint32_t bv[8][2];
            const uint32_t* v_s = (const uint32_t*)Vs;
            #pragma unroll
            for (int ni = 0; ni < 8; ni++) {
                bv[ni][0] = v_s[(k8 + tq)     * ATT_P + ni * 8 + gq];
                bv[ni][1] = v_s[(k8 + tq + 4) * ATT_P + ni * 8 + gq];
            }
            #pragma unroll
            for (int mi = 0; mi < 2; mi++)
                #pragma unroll
                for (int ni = 0; ni < 8; ni++)
                    mma_tf32(o[mi][ni], ap[mi], bv[ni]);
        }
        __syncthreads();   // readers done before next iter's K/V overwrite
    }

    // ---- write y ----
    #pragma unroll
    for (int mi = 0; mi < 2; mi++) {
        float inv0 = 1.0f / lrow[mi][0];
        float inv1 = 1.0f / lrow[mi][1];
        int r0 = qt * 128 + rb0 + mi * 16 + gq;
        #pragma unroll
        for (int ni = 0; ni < 8; ni++) {
            int col = h * HDIM + ni * 8 + 2 * tq;
            float2 w0, w1;
            w0.x = tf32_rna(o[mi][ni][0] * inv0);
            w0.y = tf32_rna(o[mi][ni][1] * inv0);
            w1.x = tf32_rna(o[mi][ni][2] * inv1);
            w1.y = tf32_rna(o[mi][ni][3] * inv1);
            *(float2*)(y + ((size_t)b * SEQ + r0) * EMBED + col) = w0;
            *(float2*)(y + ((size_t)b * SEQ + r0 + 8) * EMBED + col) = w1;
        }
    }
}

// ---------------- launch ----------------
extern "C" void kernel_launch(void* const* d_in, const int* in_sizes, int n_in,
                              void* d_out, int out_size)
{
    (void)in_sizes; (void)n_in; (void)out_size;
    const float* x      = (const float*)d_in[0];
    const float* ln1_g  = (const float*)d_in[1];
    const float* ln1_b  = (const float*)d_in[2];
    const float* w_qkv  = (const float*)d_in[3];
    const float* b_qkv  = (const float*)d_in[4];
    const float* w_out  = (const float*)d_in[5];
    const float* b_out  = (const float*)d_in[6];
    const float* ln2_g  = (const float*)d_in[7];
    const float* ln2_b  = (const float*)d_in[8];
    const float* w_up   = (const float*)d_in[9];
    const float* b_up   = (const float*)d_in[10];
    const float* w_down = (const float*)d_in[11];
    const float* b_down = (const float*)d_in[12];
    float* out = (float*)d_out;

    float *p_ln, *p_qkv, *p_y, *p_x1, *p_h;
    float *p_wqkvT, *p_woutT, *p_wupT, *p_wdownT;
    cudaGetSymbolAddress((void**)&p_ln,     g_ln);
    cudaGetSymbolAddress((void**)&p_qkv,    g_qkv);
    cudaGetSymbolAddress((void**)&p_y,      g_y);
    cudaGetSymbolAddress((void**)&p_x1,     g_x1);
    cudaGetSymbolAddress((void**)&p_h,      g_h);
    cudaGetSymbolAddress((void**)&p_wqkvT,  g_wqkvT);
    cudaGetSymbolAddress((void**)&p_woutT,  g_woutT);
    cudaGetSymbolAddress((void**)&p_wupT,   g_wupT);
    cudaGetSymbolAddress((void**)&p_wdownT, g_wdownT);

    cudaFuncSetAttribute(gemm_mma<false, false, true>,
                         cudaFuncAttributeMaxDynamicSharedMemorySize, SMEM_DYN);
    cudaFuncSetAttribute(gemm_mma<false, true, false>,
                         cudaFuncAttributeMaxDynamicSharedMemorySize, SMEM_DYN);
    cudaFuncSetAttribute(gemm_mma<true, false, true>,
                         cudaFuncAttributeMaxDynamicSharedMemorySize, SMEM_DYN);
    cudaFuncSetAttribute(attn_mma,
                         cudaFuncAttributeMaxDynamicSharedMemorySize, ATT_SMEM);

    dim3 tb(32, 8);
    // 0) transpose + tf32-round weights
    transpose_rna<<<dim3(QKV3 / 32, EMBED / 32),  tb>>>(w_qkv,  p_wqkvT,  EMBED, QKV3);
    transpose_rna<<<dim3(EMBED / 32, EMBED / 32), tb>>>(w_out,  p_woutT,  EMBED, EMBED);
    transpose_rna<<<dim3(HIDDEN / 32, EMBED / 32),tb>>>(w_up,   p_wupT,   EMBED, HIDDEN);
    transpose_rna<<<dim3(EMBED / 32, HIDDEN / 32),tb>>>(w_down, p_wdownT, HIDDEN, EMBED);

    // 1) ln1 (tf32-rounded)
    ln_kernel<<<NTOK, 256>>>(x, ln1_g, ln1_b, p_ln);
    // 2) qkv = ln1 @ w_qkv + b_qkv (tf32-rounded: feeds mma attention)
    gemm_mma<false, false, true><<<dim3(QKV3 / BN, NTOK / BM), 256, SMEM_DYN>>>(
        p_ln, p_wqkvT, b_qkv, nullptr, p_qkv, QKV3, EMBED);
    // 3) attention (tensor cores; y tf32-rounded)
    attn_mma<<<dim3(SEQ / 128, HEADS, BATCH), 128, ATT_SMEM>>>(p_qkv, p_y);
    // 4) x1 = x + y @ w_out + b_out
    gemm_mma<false, true, false><<<dim3(EMBED / BN, NTOK / BM), 256, SMEM_DYN>>>(
        p_y, p_woutT, b_out, x, p_x1, EMBED, EMBED);
    // 5) ln2 (tf32-rounded)
    ln_kernel<<<NTOK, 256>>>(p_x1, ln2_g, ln2_b, p_ln);
    // 6) h = round(relu(ln2 @ w_up + b_up))
    gemm_mma<true, false, true><<<dim3(HIDDEN / BN, NTOK / BM), 256, SMEM_DYN>>>(
        p_ln, p_wupT, b_up, nullptr, p_h, HIDDEN, EMBED);
    // 7) out = x1 + h @ w_down + b_down
    gemm_mma<false, true, false><<<dim3(EMBED / BN, NTOK / BM), 256, SMEM_DYN>>>(
        p_h, p_wdownT, b_down, p_x1, out, EMBED, HIDDEN);
}

// round 7
// speedup vs baseline: 6.3058x; 1.8276x over previous
#include <cuda_runtime.h>
#include <cuda_fp16.h>
#include <cstdint>
#include <math.h>

#define EMBED   1024
#define SEQ     1024
#define BATCH   8
#define NTOK    8192
#define HIDDEN  4096
#define HEADS   16
#define HDIM    64
#define QKV3    3072

// ---------------- scratch (no cudaMalloc allowed) ----------------
__device__ __half g_ln    [NTOK * EMBED];
__device__ __half g_qkv   [(size_t)NTOK * QKV3];
__device__ __half g_y     [NTOK * EMBED];
__device__ float  g_x1    [NTOK * EMBED];
__device__ __half g_h     [(size_t)NTOK * HIDDEN];
__device__ __half g_wqkvT [(size_t)QKV3 * EMBED];
__device__ __half g_woutT [(size_t)EMBED * EMBED];
__device__ __half g_wupT  [(size_t)HIDDEN * EMBED];
__device__ __half g_wdownT[(size_t)EMBED * HIDDEN];

// ---------------- helpers ----------------
__device__ __forceinline__ uint32_t smem_u32(const void* p) {
    uint32_t a;
    asm("{ .reg .u64 t; cvta.to.shared.u64 t, %1; cvt.u32.u64 %0, t; }" : "=r"(a) : "l"(p));
    return a;
}
__device__ __forceinline__ void cp_async16(uint32_t dst, const void* src) {
    asm volatile("cp.async.cg.shared.global [%0], [%1], 16;" :: "r"(dst), "l"(src) : "memory");
}
#define CP_COMMIT() asm volatile("cp.async.commit_group;" ::: "memory")
template <int N>
__device__ __forceinline__ void cp_wait() {
    asm volatile("cp.async.wait_group %0;" :: "n"(N) : "memory");
}

// m16n8k16 fp16 mma, fp32 accumulate (sm_80+ portable PTX)
__device__ __forceinline__ void mma_f16(float* c, const uint32_t* a, const uint32_t* b) {
    asm volatile(
        "mma.sync.aligned.m16n8k16.row.col.f32.f16.f16.f32 "
        "{%0,%1,%2,%3}, {%4,%5,%6,%7}, {%8,%9}, {%0,%1,%2,%3};"
        : "+f"(c[0]), "+f"(c[1]), "+f"(c[2]), "+f"(c[3])
        : "r"(a[0]), "r"(a[1]), "r"(a[2]), "r"(a[3]), "r"(b[0]), "r"(b[1]));
}

__device__ __forceinline__ void ldmatrix_x4_trans(uint32_t& r0, uint32_t& r1,
                                                  uint32_t& r2, uint32_t& r3,
                                                  uint32_t addr) {
    asm volatile("ldmatrix.sync.aligned.m8n8.x4.trans.shared.b16 {%0,%1,%2,%3}, [%4];"
                 : "=r"(r0), "=r"(r1), "=r"(r2), "=r"(r3) : "r"(addr));
}

// ---------------- fp16 tensor-core GEMM ----------------
// C[M,N] = A[M,K] @ Bt[N,K]^T (+bias fp32)(+res fp32)(relu), C fp32 or fp16.
// CTA tile 128M x 256N x 64K(halves), 8 warps (2x4) each 64x64, 4-stage cp.async.
#define BM 128
#define BN 256
#define BKH 64                   // K elements per stage (halves)
#define PH 72                    // pitch in halves (144B; word pitch 36 -> mod32=4)
#define PW 36                    // pitch in 32-bit words
#define A_WORDS (BM * PW)        // 4608
#define B_WORDS (BN * PW)        // 9216
#define STAGE_WORDS (A_WORDS + B_WORDS)  // 13824
#define NSTAGE 4
#define SMEM_DYN (NSTAGE * STAGE_WORDS * 4)   // 221184 bytes

template<bool RELU, bool RES, bool OUTH>
__global__ void __launch_bounds__(256, 1)
gemm_mma(const __half* __restrict__ A, const __half* __restrict__ Bt,
         const float* __restrict__ bias, const float* __restrict__ res,
         void* __restrict__ Cv, int N, int K)
{
    extern __shared__ uint32_t smw[];
    const uint32_t sbase = smem_u32(smw);
    const int tid  = threadIdx.x;
    const int wid  = tid >> 5, lane = tid & 31;
    const int gq   = lane >> 2, tq = lane & 3;
    const int wm   = wid >> 2,  wn = wid & 3;
    const int m0   = blockIdx.y * BM, n0 = blockIdx.x * BN;
    const int nk   = K / BKH;

    float acc[4][8][4];
    #pragma unroll
    for (int i = 0; i < 4; i++)
        #pragma unroll
        for (int j = 0; j < 8; j++)
            #pragma unroll
            for (int q = 0; q < 4; q++) acc[i][j][q] = 0.f;

    const __half* Ag0 = A  + (size_t)m0 * K;
    const __half* Bg0 = Bt + (size_t)n0 * K;

    auto load_stage = [&](int s, int kt) {
        uint32_t sa = sbase + (uint32_t)s * (STAGE_WORDS * 4);
        const __half* Ag = Ag0 + kt * BKH;
        #pragma unroll
        for (int j = 0; j < 4; j++) {          // A: 128 rows x 8 chunks = 1024
            int c = tid + j * 256;
            int row = c >> 3, kc = c & 7;
            cp_async16(sa + (uint32_t)(row * 144 + kc * 16),
                       Ag + (size_t)row * K + kc * 8);
        }
        uint32_t sb = sa + A_WORDS * 4;
        const __half* Bg = Bg0 + kt * BKH;
        #pragma unroll
        for (int j = 0; j < 8; j++) {          // B: 256 rows x 8 chunks = 2048
            int c = tid + j * 256;
            int row = c >> 3, kc = c & 7;
            cp_async16(sb + (uint32_t)(row * 144 + kc * 16),
                       Bg + (size_t)row * K + kc * 8);
        }
        CP_COMMIT();
    };

    load_stage(0, 0);
    load_stage(1, 1);
    load_stage(2, 2);

    for (int kt = 0; kt < nk; kt++) {
        if (kt + 2 < nk) cp_wait<2>();
        else if (kt + 1 < nk) cp_wait<1>();
        else cp_wait<0>();
        __syncthreads();
        if (kt + 3 < nk) load_stage((kt + 3) % NSTAGE, kt + 3);

        const uint32_t* a_s = smw + (kt % NSTAGE) * STAGE_WORDS;
        const uint32_t* b_s = a_s + A_WORDS;

        #pragma unroll
        for (int s = 0; s < 4; s++) {          // 4 k16 steps per BKH=64
            const int k8w = s * 8;             // word offset (16 halves)
            uint32_t af[4][4];
            #pragma unroll
            for (int mi = 0; mi < 4; mi++) {
                int rb = wm * 64 + mi * 16;
                af[mi][0] = a_s[(rb + gq)     * PW + k8w + tq];
                af[mi][1] = a_s[(rb + gq + 8) * PW + k8w + tq];
                af[mi][2] = a_s[(rb + gq)     * PW + k8w + tq + 4];
                af[mi][3] = a_s[(rb + gq + 8) * PW + k8w + tq + 4];
            }
            uint32_t bf[8][2];
            #pragma unroll
            for (int ni = 0; ni < 8; ni++) {
                int nb = wn * 64 + ni * 8;
                bf[ni][0] = b_s[(nb + gq) * PW + k8w + tq];
                bf[ni][1] = b_s[(nb + gq) * PW + k8w + tq + 4];
            }
            #pragma unroll
            for (int mi = 0; mi < 4; mi++)
                #pragma unroll
                for (int ni = 0; ni < 8; ni++)
                    mma_f16(acc[mi][ni], af[mi], bf[ni]);
        }
        __syncthreads();
    }

    // ---------- epilogue ----------
    float*  Cf = (float*)Cv;
    __half* Ch = (__half*)Cv;
    #pragma unroll
    for (int ni = 0; ni < 8; ni++) {
        int col = n0 + wn * 64 + ni * 8 + 2 * tq;
        float2 bv = __ldg((const float2*)(bias + col));
        #pragma unroll
        for (int mi = 0; mi < 4; mi++) {
            int row = m0 + wm * 64 + mi * 16 + gq;
            float2 v0, v1;
            v0.x = acc[mi][ni][0] + bv.x;
            v0.y = acc[mi][ni][1] + bv.y;
            v1.x = acc[mi][ni][2] + bv.x;
            v1.y = acc[mi][ni][3] + bv.y;
            if (RES) {
                float2 r0 = __ldg((const float2*)(res + (size_t)row * N + col));
                float2 r1 = __ldg((const float2*)(res + (size_t)(row + 8) * N + col));
                v0.x += r0.x; v0.y += r0.y;
                v1.x += r1.x; v1.y += r1.y;
            }
            if (RELU) {
                v0.x = fmaxf(v0.x, 0.f); v0.y = fmaxf(v0.y, 0.f);
                v1.x = fmaxf(v1.x, 0.f); v1.y = fmaxf(v1.y, 0.f);
            }
            if (OUTH) {
                *(__half2*)(Ch + (size_t)row * N + col)       = __floats2half2_rn(v0.x, v0.y);
                *(__half2*)(Ch + (size_t)(row + 8) * N + col) = __floats2half2_rn(v1.x, v1.y);
            } else {
                *(float2*)(Cf + (size_t)row * N + col)       = v0;
                *(float2*)(Cf + (size_t)(row + 8) * N + col) = v1;
            }
        }
    }
}

// ---------------- weight transpose + fp16 round: in[K,N] -> out[N,K] ------
__global__ void transpose_h(const float* __restrict__ in, __half* __restrict__ out,
                            int K, int N)
{
    __shared__ float t[32][33];
    int n  = blockIdx.x * 32 + threadIdx.x;
    int k0 = blockIdx.y * 32;
    #pragma unroll
    for (int r = 0; r < 32; r += 8)
        t[threadIdx.y + r][threadIdx.x] = in[(size_t)(k0 + threadIdx.y + r) * N + n];
    __syncthreads();
    int k   = k0 + threadIdx.x;
    int nn0 = blockIdx.x * 32;
    #pragma unroll
    for (int r = 0; r < 32; r += 8)
        out[(size_t)(nn0 + threadIdx.y + r) * K + k] = __float2half_rn(t[threadIdx.x][threadIdx.y + r]);
}

// ---------------- LayerNorm (fp16 output; feeds GEMMs only) ------
__global__ void ln_kernel(const float* __restrict__ x,
                          const float* __restrict__ g,
                          const float* __restrict__ b,
                          __half* __restrict__ out)
{
    int row = blockIdx.x;
    int t   = threadIdx.x;
    const float4* xr = (const float4*)(x + (size_t)row * EMBED);
    float4 v = xr[t];

    float s  = v.x + v.y + v.z + v.w;
    float s2 = v.x*v.x + v.y*v.y + v.z*v.z + v.w*v.w;
    #pragma unroll
    for (int off = 16; off > 0; off >>= 1) {
        s  += __shfl_xor_sync(0xffffffffu, s,  off);
        s2 += __shfl_xor_sync(0xffffffffu, s2, off);
    }
    __shared__ float red1[8], red2[8];
    int wid = t >> 5, lane = t & 31;
    if (lane == 0) { red1[wid] = s; red2[wid] = s2; }
    __syncthreads();
    __shared__ float s_mu, s_rstd;
    if (t == 0) {
        float ts = 0.f, ts2 = 0.f;
        #pragma unroll
        for (int i = 0; i < 8; i++) { ts += red1[i]; ts2 += red2[i]; }
        float mu  = ts * (1.0f / EMBED);
        float var = ts2 * (1.0f / EMBED) - mu * mu;
        s_mu = mu; s_rstd = rsqrtf(var + 1e-5f);
    }
    __syncthreads();
    float mu = s_mu, rstd = s_rstd;

    float4 gv = ((const float4*)g)[t];
    float4 bv = ((const float4*)b)[t];
    __half2* orow = (__half2*)(out + (size_t)row * EMBED);
    orow[2 * t]     = __floats2half2_rn((v.x - mu) * rstd * gv.x + bv.x,
                                        (v.y - mu) * rstd * gv.y + bv.y);
    orow[2 * t + 1] = __floats2half2_rn((v.z - mu) * rstd * gv.z + bv.z,
                                        (v.w - mu) * rstd * gv.w + bv.w);
}

// ---------------- flash attention via fp16 mma.sync ----------------
// BQ=128 per CTA, 4 warps (32 q-rows: 2 x m16), BK=64, D=64, KV double-buffered.
// smem (halves): Q 128x72, K[2] 64x72, V[2] 64x72, P 128x72 = 73728 bytes.
#define AQW 0                       // word offsets
#define AKW(b) (4608 + (b) * 2304)
#define AVW(b) (9216 + (b) * 2304)
#define APW 13824
#define ATT_SMEM (18432 * 4)        // 73728 bytes

__global__ void __launch_bounds__(128, 2)
attn_mma(const __half* __restrict__ qkv, __half* __restrict__ y)
{
    extern __shared__ uint32_t smw[];
    const uint32_t sbase = smem_u32(smw);

    const int qt = blockIdx.x, h = blockIdx.y, b = blockIdx.z;
    const int tid = threadIdx.x, wid = tid >> 5, lane = tid & 31;
    const int gq = lane >> 2, tq = lane & 3;
    const int rb0 = wid * 32;

    const __half* qbase = qkv + ((size_t)b * SEQ + qt * 128) * QKV3 + h * HDIM;
    const __half* kbase = qkv + (size_t)b * SEQ * QKV3 + EMBED + h * HDIM;
    const __half* vbase = kbase + EMBED;

    // Q tile: 128 rows x 8 chunks(16B) = 1024 chunks; 8 per thread
    #pragma unroll
    for (int j = 0; j < 8; j++) {
        int c = tid + j * 128;
        int row = c >> 3, kc = c & 7;
        cp_async16(sbase + AQW * 4 + (uint32_t)(row * 144 + kc * 16),
                   qbase + (size_t)row * QKV3 + kc * 8);
    }
    // KV tile 0: 64 rows x 8 chunks each = 512 chunks; 4 per thread each
    #pragma unroll
    for (int j = 0; j < 4; j++) {
        int c = tid + j * 128;
        int row = c >> 3, kc = c & 7;
        cp_async16(sbase + AKW(0) * 4 + (uint32_t)(row * 144 + kc * 16),
                   kbase + (size_t)row * QKV3 + kc * 8);
        cp_async16(sbase + AVW(0) * 4 + (uint32_t)(row * 144 + kc * 16),
                   vbase + (size_t)row * QKV3 + kc * 8);
    }
    CP_COMMIT();

    float o[2][8][4];
    float mrow[2][2], lrow[2][2];
    #pragma unroll
    for (int mi = 0; mi < 2; mi++) {
        mrow[mi][0] = mrow[mi][1] = -1e30f;
        lrow[mi][0] = lrow[mi][1] = 0.f;
        #pragma unroll
        for (int ni = 0; ni < 8; ni++)
            #pragma unroll
            for (int q = 0; q < 4; q++) o[mi][ni][q] = 0.f;
    }

    // ldmatrix V address components (x4: lanes 0-7 rows0-7/col0, 8-15 rows8-15/col0,
    // 16-23 rows0-7/col8, 24-31 rows8-15/col8)
    const int vrow = ((lane >> 3) & 1) * 8 + (lane & 7);
    const int vcol = (lane >> 4) * 8;

    const int NT = SEQ / 64;
    for (int kt = 0; kt < NT; kt++) {
        const int cur = kt & 1;
        __syncthreads();   // all warps done reading buf cur^1 (prev iter)
        if (kt + 1 < NT) {
            const int nxt = cur ^ 1;
            #pragma unroll
            for (int j = 0; j < 4; j++) {
                int c = tid + j * 128;
                int row = c >> 3, kc = c & 7;
                cp_async16(sbase + AKW(nxt) * 4 + (uint32_t)(row * 144 + kc * 16),
                           kbase + (size_t)((kt + 1) * 64 + row) * QKV3 + kc * 8);
                cp_async16(sbase + AVW(nxt) * 4 + (uint32_t)(row * 144 + kc * 16),
                           vbase + (size_t)((kt + 1) * 64 + row) * QKV3 + kc * 8);
            }
            CP_COMMIT();
            cp_wait<1>();
        } else {
            cp_wait<0>();
        }
        __syncthreads();   // buf cur visible

        const uint32_t* q_s = smw + AQW;
        const uint32_t* k_s = smw + AKW(cur);
        const uint32_t* p_s = smw + APW;

        // ---- S = Q @ K^T  (4 k16 steps over D=64) ----
        float s[2][8][4];
        #pragma unroll
        for (int mi = 0; mi < 2; mi++)
            #pragma unroll
            for (int ni = 0; ni < 8; ni++)
                #pragma unroll
                for (int q = 0; q < 4; q++) s[mi][ni][q] = 0.f;

        #pragma unroll
        for (int ks = 0; ks < 4; ks++) {
            const int k8w = ks * 8;
            uint32_t aq[2][4];
            #pragma unroll
            for (int mi = 0; mi < 2; mi++) {
                int rb = rb0 + mi * 16;
                aq[mi][0] = q_s[(rb + gq)     * PW + k8w + tq];
                aq[mi][1] = q_s[(rb + gq + 8) * PW + k8w + tq];
                aq[mi][2] = q_s[(rb + gq)     * PW + k8w + tq + 4];
                aq[mi][3] = q_s[(rb + gq + 8) * PW + k8w + tq + 4];
            }
            uint32_t bk[8][2];
            #pragma unroll
            for (int ni = 0; ni < 8; ni++) {
                bk[ni][0] = k_s[(ni * 8 + gq) * PW + k8w + tq];
                bk[ni][1] = k_s[(ni * 8 + gq) * PW + k8w + tq + 4];
            }
            #pragma unroll
            for (int mi = 0; mi < 2; mi++)
                #pragma unroll
                for (int ni = 0; ni < 8; ni++)
                    mma_f16(s[mi][ni], aq[mi], bk[ni]);
        }

        // ---- online softmax; P -> smem fp16 ----
        #pragma unroll
        for (int mi = 0; mi < 2; mi++) {
            float rm0 = -1e30f, rm1 = -1e30f;
            #pragma unroll
            for (int ni = 0; ni < 8; ni++) {
                #pragma unroll
                for (int q = 0; q < 4; q++) s[mi][ni][q] *= 0.125f;
                rm0 = fmaxf(rm0, fmaxf(s[mi][ni][0], s[mi][ni][1]));
                rm1 = fmaxf(rm1, fmaxf(s[mi][ni][2], s[mi][ni][3]));
            }
            rm0 = fmaxf(rm0, __shfl_xor_sync(0xffffffffu, rm0, 1));
            rm0 = fmaxf(rm0, __shfl_xor_sync(0xffffffffu, rm0, 2));
            rm1 = fmaxf(rm1, __shfl_xor_sync(0xffffffffu, rm1, 1));
            rm1 = fmaxf(rm1, __shfl_xor_sync(0xffffffffu, rm1, 2));

            float mn0 = fmaxf(mrow[mi][0], rm0);
            float mn1 = fmaxf(mrow[mi][1], rm1);
            float a0 = __expf(mrow[mi][0] - mn0);
            float a1 = __expf(mrow[mi][1] - mn1);
            mrow[mi][0] = mn0; mrow[mi][1] = mn1;

            float sum0 = 0.f, sum1 = 0.f;
            int rb = rb0 + mi * 16;
            uint32_t* pr0 = (uint32_t*)(smw + APW) + (rb + gq) * PW + tq;
            uint32_t* pr1 = (uint32_t*)(smw + APW) + (rb + gq + 8) * PW + tq;
            #pragma unroll
            for (int ni = 0; ni < 8; ni++) {
                float p0 = __expf(s[mi][ni][0] - mn0);
                float p1 = __expf(s[mi][ni][1] - mn0);
                float p2 = __expf(s[mi][ni][2] - mn1);
                float p3 = __expf(s[mi][ni][3] - mn1);
                sum0 += p0 + p1;
                sum1 += p2 + p3;
                __half2 hp0 = __floats2half2_rn(p0, p1);
                __half2 hp1 = __floats2half2_rn(p2, p3);
                pr0[ni * 4] = *(uint32_t*)&hp0;
                pr1[ni * 4] = *(uint32_t*)&hp1;
                o[mi][ni][0] *= a0; o[mi][ni][1] *= a0;
                o[mi][ni][2] *= a1; o[mi][ni][3] *= a1;
            }
            sum0 += __shfl_xor_sync(0xffffffffu, sum0, 1);
            sum0 += __shfl_xor_sync(0xffffffffu, sum0, 2);
            sum1 += __shfl_xor_sync(0xffffffffu, sum1, 1);
            sum1 += __shfl_xor_sync(0xffffffffu, sum1, 2);
            lrow[mi][0] = lrow[mi][0] * a0 + sum0;
            lrow[mi][1] = lrow[mi][1] * a1 + sum1;
        }
        __syncwarp();

        // ---- O += P @ V  (V^T frags via ldmatrix.trans) ----
        const uint32_t vb = sbase + AVW(cur) * 4;
        #pragma unroll
        for (int ks = 0; ks < 4; ks++) {
            const int k8w = ks * 8;
            uint32_t ap[2][4];
            #pragma unroll
            for (int mi = 0; mi < 2; mi++) {
                int rb = rb0 + mi * 16;
                ap[mi][0] = p_s[(rb + gq)     * PW + k8w + tq];
                ap[mi][1] = p_s[(rb + gq + 8) * PW + k8w + tq];
                ap[mi][2] = p_s[(rb + gq)     * PW + k8w + tq + 4];
                ap[mi][3] = p_s[(rb + gq + 8) * PW + k8w + tq + 4];
            }
            uint32_t bv[8][2];
            #pragma unroll
            for (int j = 0; j < 4; j++) {
                uint32_t addr = vb + (uint32_t)(((ks * 16 + vrow) * PH) + j * 16 + vcol) * 2;
                ldmatrix_x4_trans(bv[2 * j][0], bv[2 * j][1],
                                  bv[2 * j + 1][0], bv[2 * j + 1][1], addr);
            }
            #pragma unroll
            for (int mi = 0; mi < 2; mi++)
                #pragma unroll
                for (int ni = 0; ni < 8; ni++)
                    mma_f16(o[mi][ni], ap[mi], bv[ni]);
        }
    }

    // ---- write y (fp16; feeds out-proj GEMM) ----
    #pragma unroll
    for (int mi = 0; mi < 2; mi++) {
        float inv0 = 1.0f / lrow[mi][0];
        float inv1 = 1.0f / lrow[mi][1];
        int r0 = qt * 128 + rb0 + mi * 16 + gq;
        #pragma unroll
        for (int ni = 0; ni < 8; ni++) {
            int col = h * HDIM + ni * 8 + 2 * tq;
            *(__half2*)(y + ((size_t)b * SEQ + r0) * EMBED + col) =
                __floats2half2_rn(o[mi][ni][0] * inv0, o[mi][ni][1] * inv0);
            *(__half2*)(y + ((size_t)b * SEQ + r0 + 8) * EMBED + col) =
                __floats2half2_rn(o[mi][ni][2] * inv1, o[mi][ni][3] * inv1);
        }
    }
}

// ---------------- launch ----------------
extern "C" void kernel_launch(void* const* d_in, const int* in_sizes, int n_in,
                              void* d_out, int out_size)
{
    (void)in_sizes; (void)n_in; (void)out_size;
    const float* x      = (const float*)d_in[0];
    const float* ln1_g  = (const float*)d_in[1];
    const float* ln1_b  = (const float*)d_in[2];
    const float* w_qkv  = (const float*)d_in[3];
    const float* b_qkv  = (const float*)d_in[4];
    const float* w_out  = (const float*)d_in[5];
    const float* b_out  = (const float*)d_in[6];
    const float* ln2_g  = (const float*)d_in[7];
    const float* ln2_b  = (const float*)d_in[8];
    const float* w_up   = (const float*)d_in[9];
    const float* b_up   = (const float*)d_in[10];
    const float* w_down = (const float*)d_in[11];
    const float* b_down = (const float*)d_in[12];
    float* out = (float*)d_out;

    __half *p_ln, *p_qkv, *p_y, *p_h;
    float *p_x1;
    __half *p_wqkvT, *p_woutT, *p_wupT, *p_wdownT;
    cudaGetSymbolAddress((void**)&p_ln,     g_ln);
    cudaGetSymbolAddress((void**)&p_qkv,    g_qkv);
    cudaGetSymbolAddress((void**)&p_y,      g_y);
    cudaGetSymbolAddress((void**)&p_x1,     g_x1);
    cudaGetSymbolAddress((void**)&p_h,      g_h);
    cudaGetSymbolAddress((void**)&p_wqkvT,  g_wqkvT);
    cudaGetSymbolAddress((void**)&p_woutT,  g_woutT);
    cudaGetSymbolAddress((void**)&p_wupT,   g_wupT);
    cudaGetSymbolAddress((void**)&p_wdownT, g_wdownT);

    cudaFuncSetAttribute(gemm_mma<false, false, true>,
                         cudaFuncAttributeMaxDynamicSharedMemorySize, SMEM_DYN);
    cudaFuncSetAttribute(gemm_mma<false, true, false>,
                         cudaFuncAttributeMaxDynamicSharedMemorySize, SMEM_DYN);
    cudaFuncSetAttribute(gemm_mma<true, false, true>,
                         cudaFuncAttributeMaxDynamicSharedMemorySize, SMEM_DYN);
    cudaFuncSetAttribute(attn_mma,
                         cudaFuncAttributeMaxDynamicSharedMemorySize, ATT_SMEM);

    dim3 tb(32, 8);
    // 0) transpose + fp16 round weights
    transpose_h<<<dim3(QKV3 / 32, EMBED / 32),  tb>>>(w_qkv,  p_wqkvT,  EMBED, QKV3);
    transpose_h<<<dim3(EMBED / 32, EMBED / 32), tb>>>(w_out,  p_woutT,  EMBED, EMBED);
    transpose_h<<<dim3(HIDDEN / 32, EMBED / 32),tb>>>(w_up,   p_wupT,   EMBED, HIDDEN);
    transpose_h<<<dim3(EMBED / 32, HIDDEN / 32),tb>>>(w_down, p_wdownT, HIDDEN, EMBED);

    // 1) ln1 (fp16 out)
    ln_kernel<<<NTOK, 256>>>(x, ln1_g, ln1_b, p_ln);
    // 2) qkv = ln1 @ w_qkv + b_qkv  (fp16 out -> attention)
    gemm_mma<false, false, true><<<dim3(QKV3 / BN, NTOK / BM), 256, SMEM_DYN>>>(
        p_ln, p_wqkvT, b_qkv, nullptr, p_qkv, QKV3, EMBED);
    // 3) attention (fp16 mma; y fp16)
    attn_mma<<<dim3(SEQ / 128, HEADS, BATCH), 128, ATT_SMEM>>>(p_qkv, p_y);
    // 4) x1 = x + y @ w_out + b_out  (fp32 out)
    gemm_mma<false, true, false><<<dim3(EMBED / BN, NTOK / BM), 256, SMEM_DYN>>>(
        p_y, p_woutT, b_out, x, p_x1, EMBED, EMBED);
    // 5) ln2 (fp16 out)
    ln_kernel<<<NTOK, 256>>>(p_x1, ln2_g, ln2_b, p_ln);
    // 6) h = relu(ln2 @ w_up + b_up)  (fp16 out)
    gemm_mma<true, false, true><<<dim3(HIDDEN / BN, NTOK / BM), 256, SMEM_DYN>>>(
        p_ln, p_wupT, b_up, nullptr, p_h, HIDDEN, EMBED);
    // 7) out = x1 + h @ w_down + b_down  (fp32 out)
    gemm_mma<false, true, false><<<dim3(EMBED / BN, NTOK / BM), 256, SMEM_DYN>>>(
        p_h, p_wdownT, b_down, p_x1, out, EMBED, HIDDEN);
}